// round 1
// baseline (speedup 1.0000x reference)
#include <cuda_runtime.h>
#include <math.h>

// Problem constants
#define BB 32
#define CC 64
#define LL 2048
#define DD 50
#define DP 52   // padded K/Q feature stride (multiple of 4 for float4)

// Scratch (device globals — no allocation allowed)
__device__ float g_K[BB * LL * DP];     // elu(x Wk + bk), padded with zeros
__device__ float g_Q[BB * LL * DP];     // elu(x Wq + bq), padded with zeros
__device__ float g_V[BB * LL * CC];     // tanh(x Wv + bv)
__device__ float g_cinv[BB * LL];       // 1 / sum_l exp(s[l,m]*scale)  per (b,m)

// sample_len may arrive as int32 / int64 / float32 — decode robustly.
__device__ __forceinline__ float read_len(const void* p) {
    int i = *(const int*)p;
    if (i > 0 && i < (1 << 24)) return (float)i;   // int32 or low word of int64
    return __int_as_float(i);                       // float32 encoding
}

// ---------------------------------------------------------------------------
// Kernel 1: K/Q/V projections + activations.
// grid (L/128, B), 128 threads. Each thread owns one l; x row in registers,
// weights staged TRANSPOSED in shared so inner products read float4 rows.
// ---------------------------------------------------------------------------
__global__ void kqv_kernel(const float* __restrict__ x,
                           const float* __restrict__ Wk, const float* __restrict__ bk,
                           const float* __restrict__ Wq, const float* __restrict__ bq,
                           const float* __restrict__ Wv, const float* __restrict__ bv) {
    __shared__ float WkT[DD * CC];   // [d][c]
    __shared__ float WqT[DD * CC];
    __shared__ float WvT[CC * CC];   // [o][c]
    __shared__ float bks[DD], bqs[DD], bvs[CC];

    const int tid = threadIdx.x;
    const int b = blockIdx.y;
    const int l = blockIdx.x * 128 + tid;

    for (int idx = tid; idx < CC * DD; idx += 128) {
        int c = idx / DD, d = idx % DD;
        WkT[d * CC + c] = Wk[idx];
        WqT[d * CC + c] = Wq[idx];
    }
    for (int idx = tid; idx < CC * CC; idx += 128) {
        int c = idx / CC, o = idx % CC;
        WvT[o * CC + c] = Wv[idx];
    }
    if (tid < DD) { bks[tid] = bk[tid]; bqs[tid] = bq[tid]; }
    if (tid < CC) { bvs[tid] = bv[tid]; }
    __syncthreads();

    // x is [B, C, L]: column l of batch b, coalesced across threads per c.
    float xr[CC];
    const float* xb = x + (size_t)b * CC * LL + l;
#pragma unroll
    for (int c = 0; c < CC; c++) xr[c] = xb[(size_t)c * LL];

    float* Krow = g_K + ((size_t)b * LL + l) * DP;
    float* Qrow = g_Q + ((size_t)b * LL + l) * DP;
    float* Vrow = g_V + ((size_t)b * LL + l) * CC;

    for (int d = 0; d < DD; d++) {
        float ak = bks[d], aq = bqs[d];
        const float4* wk4 = (const float4*)&WkT[d * CC];
        const float4* wq4 = (const float4*)&WqT[d * CC];
#pragma unroll
        for (int c4 = 0; c4 < CC / 4; c4++) {
            float4 wk = wk4[c4];
            float4 wq = wq4[c4];
            ak = fmaf(xr[4 * c4 + 0], wk.x, ak);
            ak = fmaf(xr[4 * c4 + 1], wk.y, ak);
            ak = fmaf(xr[4 * c4 + 2], wk.z, ak);
            ak = fmaf(xr[4 * c4 + 3], wk.w, ak);
            aq = fmaf(xr[4 * c4 + 0], wq.x, aq);
            aq = fmaf(xr[4 * c4 + 1], wq.y, aq);
            aq = fmaf(xr[4 * c4 + 2], wq.z, aq);
            aq = fmaf(xr[4 * c4 + 3], wq.w, aq);
        }
        Krow[d] = (ak > 0.0f) ? ak : expm1f(ak);   // elu
        Qrow[d] = (aq > 0.0f) ? aq : expm1f(aq);
    }
    Krow[DD] = 0.0f; Krow[DD + 1] = 0.0f;
    Qrow[DD] = 0.0f; Qrow[DD + 1] = 0.0f;

    for (int o = 0; o < CC; o++) {
        float av = bvs[o];
        const float4* wv4 = (const float4*)&WvT[o * CC];
#pragma unroll
        for (int c4 = 0; c4 < CC / 4; c4++) {
            float4 wv = wv4[c4];
            av = fmaf(xr[4 * c4 + 0], wv.x, av);
            av = fmaf(xr[4 * c4 + 1], wv.y, av);
            av = fmaf(xr[4 * c4 + 2], wv.z, av);
            av = fmaf(xr[4 * c4 + 3], wv.w, av);
        }
        Vrow[o] = tanhf(av);
    }
}

// ---------------------------------------------------------------------------
// Kernel 2: column softmax denominators.
// softmax over axis=1 (over l, per m): cinv[b,m] = 1 / sum_l exp(k[l]·q[m]·scale)
// Scores are ~N(0, 0.4): exp never overflows, no max-subtraction needed.
// grid (L/128, B), 128 threads; thread owns m, q in registers, K tiles in shared
// (broadcast float4 LDS — all threads read same address).
// ---------------------------------------------------------------------------
__global__ void colsum_kernel(const void* __restrict__ slp) {
    __shared__ float k_s[128 * DP];   // 26 KB
    const int tid = threadIdx.x;
    const int b = blockIdx.y;
    const int m = blockIdx.x * 128 + tid;
    const float scale = rsqrtf(read_len(slp));

    float4 q4[DP / 4];
    const float4* qg = (const float4*)(g_Q + ((size_t)b * LL + m) * DP);
#pragma unroll
    for (int i = 0; i < DP / 4; i++) q4[i] = qg[i];

    float sum = 0.0f;
    for (int lt = 0; lt < LL / 128; lt++) {
        const float4* kg = (const float4*)(g_K + ((size_t)b * LL + lt * 128) * DP);
        float4* ks4 = (float4*)k_s;
#pragma unroll
        for (int i = 0; i < DP / 4; i++) ks4[tid + 128 * i] = kg[tid + 128 * i];
        __syncthreads();

        for (int l = 0; l < 128; l++) {
            const float4* kr = (const float4*)&k_s[l * DP];
            float s0 = 0.0f, s1 = 0.0f, s2 = 0.0f, s3 = 0.0f;
#pragma unroll
            for (int i = 0; i < DP / 4; i++) {
                float4 kv = kr[i];
                s0 = fmaf(q4[i].x, kv.x, s0);
                s1 = fmaf(q4[i].y, kv.y, s1);
                s2 = fmaf(q4[i].z, kv.z, s2);
                s3 = fmaf(q4[i].w, kv.w, s3);
            }
            sum += __expf(((s0 + s1) + (s2 + s3)) * scale);
        }
        __syncthreads();
    }
    g_cinv[(size_t)b * LL + m] = 1.0f / sum;
}

// ---------------------------------------------------------------------------
// Kernel 3: y[b,l,c] = sum_m exp(s[l,m]*scale) * cinv[b,m] * v[m,c]
// grid (L/64, B), 256 threads (16x16), each thread a 4x4 micro-tile.
// K/Q tiles staged transposed ([d][l] / [d][m]) for conflict-free float4 LDS.
// P tile goes through shared (padded stride 65).
// ---------------------------------------------------------------------------
__global__ void out_kernel(float* __restrict__ out, const void* __restrict__ slp) {
    extern __shared__ float sm[];
    float* kT = sm;                 // [50][64]  -> 3200
    float* qT = kT + DD * 64;       // [50][64]  -> 3200
    float* vs = qT + DD * 64;       // [64][64]  -> 4096
    float* ps = vs + 64 * 64;       // [64][65]  -> 4160
    float* ci = ps + 64 * 65;       // [64]

    const int tid = threadIdx.x;
    const int b = blockIdx.y;
    const int l0 = blockIdx.x * 64;
    const int tr = tid >> 4;        // 0..15 -> l rows 4*tr..4*tr+3
    const int tc = tid & 15;        // 0..15 -> m/c cols 4*tc..4*tc+3
    const float scale = rsqrtf(read_len(slp));

    // Stage K tile once (transposed)
    for (int idx = tid; idx < 64 * DD; idx += 256) {
        int l = idx / DD, d = idx % DD;
        kT[d * 64 + l] = g_K[((size_t)b * LL + l0 + l) * DP + d];
    }

    float acc[4][4];
#pragma unroll
    for (int i = 0; i < 4; i++)
#pragma unroll
        for (int j = 0; j < 4; j++) acc[i][j] = 0.0f;

    for (int mt = 0; mt < LL / 64; mt++) {
        const int m0 = mt * 64;
        __syncthreads();   // protects kT first time; qT/vs/ps reuse afterwards

        for (int idx = tid; idx < 64 * DD; idx += 256) {
            int mm = idx / DD, d = idx % DD;
            qT[d * 64 + mm] = g_Q[((size_t)b * LL + m0 + mm) * DP + d];
        }
        {
            const float4* vg = (const float4*)(g_V + ((size_t)b * LL + m0) * CC);
            float4* v4 = (float4*)vs;
#pragma unroll
            for (int i = 0; i < 4; i++) v4[tid + 256 * i] = vg[tid + 256 * i];
        }
        if (tid < 64) ci[tid] = g_cinv[(size_t)b * LL + m0 + tid];
        __syncthreads();

        // Phase A: S = K_tile @ Q_tile^T  (4x4 per thread over d)
        float s[4][4];
#pragma unroll
        for (int i = 0; i < 4; i++)
#pragma unroll
            for (int j = 0; j < 4; j++) s[i][j] = 0.0f;

        for (int d = 0; d < DD; d++) {
            float4 kv = *(const float4*)&kT[d * 64 + 4 * tr];
            float4 qv = *(const float4*)&qT[d * 64 + 4 * tc];
            s[0][0] = fmaf(kv.x, qv.x, s[0][0]);
            s[0][1] = fmaf(kv.x, qv.y, s[0][1]);
            s[0][2] = fmaf(kv.x, qv.z, s[0][2]);
            s[0][3] = fmaf(kv.x, qv.w, s[0][3]);
            s[1][0] = fmaf(kv.y, qv.x, s[1][0]);
            s[1][1] = fmaf(kv.y, qv.y, s[1][1]);
            s[1][2] = fmaf(kv.y, qv.z, s[1][2]);
            s[1][3] = fmaf(kv.y, qv.w, s[1][3]);
            s[2][0] = fmaf(kv.z, qv.x, s[2][0]);
            s[2][1] = fmaf(kv.z, qv.y, s[2][1]);
            s[2][2] = fmaf(kv.z, qv.z, s[2][2]);
            s[2][3] = fmaf(kv.z, qv.w, s[2][3]);
            s[3][0] = fmaf(kv.w, qv.x, s[3][0]);
            s[3][1] = fmaf(kv.w, qv.y, s[3][1]);
            s[3][2] = fmaf(kv.w, qv.z, s[3][2]);
            s[3][3] = fmaf(kv.w, qv.w, s[3][3]);
        }
        // P = exp(S*scale) * cinv[m], into padded shared
        float cv0 = ci[4 * tc + 0], cv1 = ci[4 * tc + 1];
        float cv2 = ci[4 * tc + 2], cv3 = ci[4 * tc + 3];
#pragma unroll
        for (int i = 0; i < 4; i++) {
            float* pr = &ps[(4 * tr + i) * 65 + 4 * tc];
            pr[0] = __expf(s[i][0] * scale) * cv0;
            pr[1] = __expf(s[i][1] * scale) * cv1;
            pr[2] = __expf(s[i][2] * scale) * cv2;
            pr[3] = __expf(s[i][3] * scale) * cv3;
        }
        __syncthreads();

        // Phase C: Y += P @ V
        for (int kk = 0; kk < 64; kk++) {
            float4 vv = *(const float4*)&vs[kk * 64 + 4 * tc];
            float p0 = ps[(4 * tr + 0) * 65 + kk];
            float p1 = ps[(4 * tr + 1) * 65 + kk];
            float p2 = ps[(4 * tr + 2) * 65 + kk];
            float p3 = ps[(4 * tr + 3) * 65 + kk];
            acc[0][0] = fmaf(p0, vv.x, acc[0][0]);
            acc[0][1] = fmaf(p0, vv.y, acc[0][1]);
            acc[0][2] = fmaf(p0, vv.z, acc[0][2]);
            acc[0][3] = fmaf(p0, vv.w, acc[0][3]);
            acc[1][0] = fmaf(p1, vv.x, acc[1][0]);
            acc[1][1] = fmaf(p1, vv.y, acc[1][1]);
            acc[1][2] = fmaf(p1, vv.z, acc[1][2]);
            acc[1][3] = fmaf(p1, vv.w, acc[1][3]);
            acc[2][0] = fmaf(p2, vv.x, acc[2][0]);
            acc[2][1] = fmaf(p2, vv.y, acc[2][1]);
            acc[2][2] = fmaf(p2, vv.z, acc[2][2]);
            acc[2][3] = fmaf(p2, vv.w, acc[2][3]);
            acc[3][0] = fmaf(p3, vv.x, acc[3][0]);
            acc[3][1] = fmaf(p3, vv.y, acc[3][1]);
            acc[3][2] = fmaf(p3, vv.z, acc[3][2]);
            acc[3][3] = fmaf(p3, vv.w, acc[3][3]);
        }
    }

    // Write y[b, l, c], float4 per row
#pragma unroll
    for (int i = 0; i < 4; i++) {
        float4 o = make_float4(acc[i][0], acc[i][1], acc[i][2], acc[i][3]);
        *(float4*)&out[((size_t)b * LL + l0 + 4 * tr + i) * CC + 4 * tc] = o;
    }
}

// ---------------------------------------------------------------------------
extern "C" void kernel_launch(void* const* d_in, const int* in_sizes, int n_in,
                              void* d_out, int out_size) {
    const float* x  = (const float*)d_in[0];
    const float* Wk = (const float*)d_in[1];
    const float* bk = (const float*)d_in[2];
    const float* Wq = (const float*)d_in[3];
    const float* bq = (const float*)d_in[4];
    const float* Wv = (const float*)d_in[5];
    const float* bv = (const float*)d_in[6];
    const void*  sl = (const void*)d_in[7];
    float* out = (float*)d_out;

    static bool attr_set = false;
    const int smem3 = (DD * 64 + DD * 64 + 64 * 64 + 64 * 65 + 64) * (int)sizeof(float);
    if (!attr_set) {
        cudaFuncSetAttribute(out_kernel, cudaFuncAttributeMaxDynamicSharedMemorySize, smem3);
        attr_set = true;
    }

    dim3 g1(LL / 128, BB);
    kqv_kernel<<<g1, 128>>>(x, Wk, bk, Wq, bq, Wv, bv);

    dim3 g2(LL / 128, BB);
    colsum_kernel<<<g2, 128>>>(sl);

    dim3 g3(LL / 64, BB);
    out_kernel<<<g3, 256, smem3>>>(out, sl);
}

// round 3
// speedup vs baseline: 1.3811x; 1.3811x over previous
#include <cuda_runtime.h>
#include <mma.h>
#include <math.h>
#include <stdint.h>

using namespace nvcuda;

// Problem constants
#define BB 32
#define CC 64
#define LL 2048
#define DD 50
#define DK 64          // padded feature dim (GEMM1 K-dim)
#define TL 128         // l-tile (rows)
#define TM 128         // m-tile (cols of S / K-dim of GEMM2)
#define NLT (LL/TL)    // 16
#define NMT (LL/TM)    // 16

#define KS_LD 72       // SMEM leading dim for K/Q tiles (64 + 8 pad)
#define SS_LD 136      // SMEM leading dim for S/P/V' tiles (128 + 8 pad)

// Scratch (device globals — allocation is forbidden)
__device__ float g_K[BB*LL*DK];      // tf32(elu(xWk+bk)), d-major, zero padded
__device__ float g_Q[BB*LL*DK];
__device__ float g_V[BB*LL*CC];      // tanh(xWv+bv), c-major (fp32)
__device__ float g_Vt[BB*CC*LL];     // tf32( V[b][m][c] * cinv[b][m] ), [b][c][m]
__device__ float g_part[NLT*BB*LL];  // per-ltile column partial sums

__device__ __forceinline__ float read_len(const void* p) {
    int i = *(const int*)p;
    if (i > 0 && i < (1 << 24)) return (float)i;   // int32 / low word of int64
    return __int_as_float(i);                       // float32 encoding
}

// ---------------------------------------------------------------------------
// Kernel 1: K/Q/V projections + activations. K/Q zero-padded to 64, tf32-rounded.
// grid (L/128, B), 128 threads; thread owns one l.
// ---------------------------------------------------------------------------
__global__ void kqv_kernel(const float* __restrict__ x,
                           const float* __restrict__ Wk, const float* __restrict__ bk,
                           const float* __restrict__ Wq, const float* __restrict__ bq,
                           const float* __restrict__ Wv, const float* __restrict__ bv) {
    __shared__ float WkT[DD * CC];   // [d][c]
    __shared__ float WqT[DD * CC];
    __shared__ float WvT[CC * CC];   // [o][c]
    __shared__ float bks[DD], bqs[DD], bvs[CC];

    const int tid = threadIdx.x;
    const int b = blockIdx.y;
    const int l = blockIdx.x * 128 + tid;

    for (int idx = tid; idx < CC * DD; idx += 128) {
        int c = idx / DD, d = idx % DD;
        WkT[d * CC + c] = Wk[idx];
        WqT[d * CC + c] = Wq[idx];
    }
    for (int idx = tid; idx < CC * CC; idx += 128) {
        int c = idx / CC, o = idx % CC;
        WvT[o * CC + c] = Wv[idx];
    }
    if (tid < DD) { bks[tid] = bk[tid]; bqs[tid] = bq[tid]; }
    if (tid < CC) { bvs[tid] = bv[tid]; }
    __syncthreads();

    float xr[CC];
    const float* xb = x + (size_t)b * CC * LL + l;
#pragma unroll
    for (int c = 0; c < CC; c++) xr[c] = xb[(size_t)c * LL];

    float* Krow = g_K + ((size_t)b * LL + l) * DK;
    float* Qrow = g_Q + ((size_t)b * LL + l) * DK;
    float* Vrow = g_V + ((size_t)b * LL + l) * CC;

    for (int d = 0; d < DD; d++) {
        float ak = bks[d], aq = bqs[d];
        const float4* wk4 = (const float4*)&WkT[d * CC];
        const float4* wq4 = (const float4*)&WqT[d * CC];
#pragma unroll
        for (int c4 = 0; c4 < CC / 4; c4++) {
            float4 wk = wk4[c4], wq = wq4[c4];
            ak = fmaf(xr[4*c4+0], wk.x, ak); ak = fmaf(xr[4*c4+1], wk.y, ak);
            ak = fmaf(xr[4*c4+2], wk.z, ak); ak = fmaf(xr[4*c4+3], wk.w, ak);
            aq = fmaf(xr[4*c4+0], wq.x, aq); aq = fmaf(xr[4*c4+1], wq.y, aq);
            aq = fmaf(xr[4*c4+2], wq.z, aq); aq = fmaf(xr[4*c4+3], wq.w, aq);
        }
        float ek = (ak > 0.0f) ? ak : expm1f(ak);
        float eq = (aq > 0.0f) ? aq : expm1f(aq);
        Krow[d] = wmma::__float_to_tf32(ek);
        Qrow[d] = wmma::__float_to_tf32(eq);
    }
#pragma unroll
    for (int d = DD; d < DK; d++) { Krow[d] = 0.0f; Qrow[d] = 0.0f; }

    for (int o = 0; o < CC; o++) {
        float av = bvs[o];
        const float4* wv4 = (const float4*)&WvT[o * CC];
#pragma unroll
        for (int c4 = 0; c4 < CC / 4; c4++) {
            float4 wv = wv4[c4];
            av = fmaf(xr[4*c4+0], wv.x, av); av = fmaf(xr[4*c4+1], wv.y, av);
            av = fmaf(xr[4*c4+2], wv.z, av); av = fmaf(xr[4*c4+3], wv.w, av);
        }
        Vrow[o] = tanhf(av);
    }
}

// ---------------------------------------------------------------------------
// Kernel 2: column partial sums via wmma tf32.
// grid (NLT, BB), 256 threads (8 warps). Warp w = rows [16w, 16w+16).
// Per m-tile: S = K@Q^T (wmma), exp in-register, store padded SMEM, col-reduce.
// ---------------------------------------------------------------------------
#define SM1_FLOATS (TL*KS_LD + TM*KS_LD + TL*SS_LD + 256)

__global__ __launch_bounds__(256, 1) void colsum_wmma(const void* __restrict__ slp) {
    extern __shared__ float sm[];
    float* Ks  = sm;                       // [128][72]
    float* Qs  = Ks + TL * KS_LD;          // [128][72]
    float* Ss  = Qs + TM * KS_LD;          // [128][136]
    float* red = Ss + TL * SS_LD;          // [256]

    const int tid = threadIdx.x;
    const int wid = tid >> 5;
    const int b = blockIdx.y;
    const int l0 = blockIdx.x * TL;
    const int r0 = wid * 16;
    const float scale = rsqrtf(read_len(slp));

    // Stage K tile once
    for (int idx = tid; idx < TL * (DK / 4); idx += 256) {
        int row = idx >> 4, c4 = idx & 15;
        float4 v = *(const float4*)(g_K + ((size_t)b * LL + l0 + row) * DK + (c4 << 2));
        *(float4*)&Ks[row * KS_LD + (c4 << 2)] = v;
    }

    for (int mt = 0; mt < NMT; mt++) {
        const int m0 = mt * TM;
        for (int idx = tid; idx < TM * (DK / 4); idx += 256) {
            int row = idx >> 4, c4 = idx & 15;
            float4 v = *(const float4*)(g_Q + ((size_t)b * LL + m0 + row) * DK + (c4 << 2));
            *(float4*)&Qs[row * KS_LD + (c4 << 2)] = v;
        }
        __syncthreads();

        wmma::fragment<wmma::accumulator, 16, 16, 8, float> acc[8];
#pragma unroll
        for (int j = 0; j < 8; j++) wmma::fill_fragment(acc[j], 0.0f);

#pragma unroll
        for (int ks = 0; ks < DK / 8; ks++) {
            wmma::fragment<wmma::matrix_a, 16, 16, 8, wmma::precision::tf32, wmma::row_major> a;
            wmma::load_matrix_sync(a, &Ks[r0 * KS_LD + 8 * ks], KS_LD);
#pragma unroll
            for (int j = 0; j < 8; j++) {
                wmma::fragment<wmma::matrix_b, 16, 16, 8, wmma::precision::tf32, wmma::col_major> bf;
                wmma::load_matrix_sync(bf, &Qs[(16 * j) * KS_LD + 8 * ks], KS_LD);
                wmma::mma_sync(acc[j], a, bf, acc[j]);
            }
        }

#pragma unroll
        for (int j = 0; j < 8; j++) {
#pragma unroll
            for (int e = 0; e < acc[j].num_elements; e++)
                acc[j].x[e] = __expf(acc[j].x[e] * scale);
            wmma::store_matrix_sync(&Ss[r0 * SS_LD + 16 * j], acc[j], SS_LD, wmma::mem_row_major);
        }
        __syncthreads();

        // column reduce: 256 threads, two row-halves per column
        {
            const int col = tid & 127, half = tid >> 7;
            float s = 0.0f;
            const float* base = &Ss[(half * 64) * SS_LD + col];
#pragma unroll 8
            for (int l = 0; l < 64; l++) s += base[l * SS_LD];
            red[tid] = s;
        }
        __syncthreads();
        if (tid < 128)
            g_part[((size_t)blockIdx.x * BB + b) * LL + m0 + tid] = red[tid] + red[tid + 128];
        __syncthreads();
    }
}

// ---------------------------------------------------------------------------
// Kernel 3: cinv + scaled transposed V (tf32-rounded). grid (LL/64, BB), 256 thr.
// ---------------------------------------------------------------------------
__global__ void prep_kernel() {
    __shared__ float ci[64];
    __shared__ float vt[64 * 68];
    const int tid = threadIdx.x;
    const int b = blockIdx.y;
    const int m0 = blockIdx.x * 64;

    if (tid < 64) {
        float s = 0.0f;
#pragma unroll
        for (int lt = 0; lt < NLT; lt++)
            s += g_part[((size_t)lt * BB + b) * LL + m0 + tid];
        ci[tid] = 1.0f / s;
    }
    for (int idx = tid; idx < 64 * 16; idx += 256) {
        int row = idx >> 4, c4 = idx & 15;
        float4 v = *(const float4*)(g_V + ((size_t)b * LL + m0 + row) * CC + (c4 << 2));
        *(float4*)&vt[row * 68 + (c4 << 2)] = v;
    }
    __syncthreads();
    for (int idx = tid; idx < 64 * 16; idx += 256) {
        int c = idx >> 4, m4 = idx & 15;
        float4 o;
        o.x = wmma::__float_to_tf32(vt[(m4 * 4 + 0) * 68 + c] * ci[m4 * 4 + 0]);
        o.y = wmma::__float_to_tf32(vt[(m4 * 4 + 1) * 68 + c] * ci[m4 * 4 + 1]);
        o.z = wmma::__float_to_tf32(vt[(m4 * 4 + 2) * 68 + c] * ci[m4 * 4 + 2]);
        o.w = wmma::__float_to_tf32(vt[(m4 * 4 + 3) * 68 + c] * ci[m4 * 4 + 3]);
        *(float4*)(g_Vt + ((size_t)b * CC + c) * LL + m0 + (m4 << 2)) = o;
    }
}

// ---------------------------------------------------------------------------
// Kernel 4: Y = P @ V'  fully on wmma tf32.
// grid (NLT, BB), 256 threads. Per m-tile: GEMM1 S=K@Q^T, exp (+tf32 round)
// in-register, P through SMEM, GEMM2 Y += P @ V'. Y persists in fragments.
// ---------------------------------------------------------------------------
#define SM2_FLOATS (TL*KS_LD + TM*KS_LD + CC*SS_LD + TL*SS_LD)

__global__ __launch_bounds__(256, 1) void out_wmma(float* __restrict__ out,
                                                   const void* __restrict__ slp) {
    extern __shared__ float sm[];
    float* Ks = sm;                        // [128][72]
    float* Qs = Ks + TL * KS_LD;           // [128][72]
    float* Vs = Qs + TM * KS_LD;           // [64 c][136] (cols = m)
    float* Ps = Vs + CC * SS_LD;           // [128 l][136] (cols = m)

    const int tid = threadIdx.x;
    const int wid = tid >> 5;
    const int b = blockIdx.y;
    const int l0 = blockIdx.x * TL;
    const int r0 = wid * 16;
    const float scale = rsqrtf(read_len(slp));

    for (int idx = tid; idx < TL * (DK / 4); idx += 256) {
        int row = idx >> 4, c4 = idx & 15;
        float4 v = *(const float4*)(g_K + ((size_t)b * LL + l0 + row) * DK + (c4 << 2));
        *(float4*)&Ks[row * KS_LD + (c4 << 2)] = v;
    }

    wmma::fragment<wmma::accumulator, 16, 16, 8, float> yacc[4];
#pragma unroll
    for (int j = 0; j < 4; j++) wmma::fill_fragment(yacc[j], 0.0f);

    for (int mt = 0; mt < NMT; mt++) {
        const int m0 = mt * TM;
        for (int idx = tid; idx < TM * (DK / 4); idx += 256) {
            int row = idx >> 4, c4 = idx & 15;
            float4 v = *(const float4*)(g_Q + ((size_t)b * LL + m0 + row) * DK + (c4 << 2));
            *(float4*)&Qs[row * KS_LD + (c4 << 2)] = v;
        }
        for (int idx = tid; idx < CC * (TM / 4); idx += 256) {
            int row = idx >> 5, c4 = idx & 31;
            float4 v = *(const float4*)(g_Vt + ((size_t)b * CC + row) * LL + m0 + (c4 << 2));
            *(float4*)&Vs[row * SS_LD + (c4 << 2)] = v;
        }
        __syncthreads();

        // GEMM1: S = K @ Q^T
        wmma::fragment<wmma::accumulator, 16, 16, 8, float> acc[8];
#pragma unroll
        for (int j = 0; j < 8; j++) wmma::fill_fragment(acc[j], 0.0f);
#pragma unroll
        for (int ks = 0; ks < DK / 8; ks++) {
            wmma::fragment<wmma::matrix_a, 16, 16, 8, wmma::precision::tf32, wmma::row_major> a;
            wmma::load_matrix_sync(a, &Ks[r0 * KS_LD + 8 * ks], KS_LD);
#pragma unroll
            for (int j = 0; j < 8; j++) {
                wmma::fragment<wmma::matrix_b, 16, 16, 8, wmma::precision::tf32, wmma::col_major> bf;
                wmma::load_matrix_sync(bf, &Qs[(16 * j) * KS_LD + 8 * ks], KS_LD);
                wmma::mma_sync(acc[j], a, bf, acc[j]);
            }
        }
        // P = tf32(exp(S*scale)) into SMEM
#pragma unroll
        for (int j = 0; j < 8; j++) {
#pragma unroll
            for (int e = 0; e < acc[j].num_elements; e++)
                acc[j].x[e] = wmma::__float_to_tf32(__expf(acc[j].x[e] * scale));
            wmma::store_matrix_sync(&Ps[r0 * SS_LD + 16 * j], acc[j], SS_LD, wmma::mem_row_major);
        }
        __syncthreads();

        // GEMM2: Y += P @ V'   (K-dim = 128 m, 16 k-steps)
#pragma unroll
        for (int ks = 0; ks < TM / 8; ks++) {
            wmma::fragment<wmma::matrix_a, 16, 16, 8, wmma::precision::tf32, wmma::row_major> a;
            wmma::load_matrix_sync(a, &Ps[r0 * SS_LD + 8 * ks], SS_LD);
#pragma unroll
            for (int jc = 0; jc < 4; jc++) {
                wmma::fragment<wmma::matrix_b, 16, 16, 8, wmma::precision::tf32, wmma::col_major> bf;
                wmma::load_matrix_sync(bf, &Vs[(16 * jc) * SS_LD + 8 * ks], SS_LD);
                wmma::mma_sync(yacc[jc], a, bf, yacc[jc]);
            }
        }
        __syncthreads();
    }

    // Write Y directly from fragments to global
#pragma unroll
    for (int jc = 0; jc < 4; jc++)
        wmma::store_matrix_sync(&out[((size_t)b * LL + l0 + r0) * CC + 16 * jc],
                                yacc[jc], CC, wmma::mem_row_major);
}

// ---------------------------------------------------------------------------
extern "C" void kernel_launch(void* const* d_in, const int* in_sizes, int n_in,
                              void* d_out, int out_size) {
    const float* x  = (const float*)d_in[0];
    const float* Wk = (const float*)d_in[1];
    const float* bk = (const float*)d_in[2];
    const float* Wq = (const float*)d_in[3];
    const float* bq = (const float*)d_in[4];
    const float* Wv = (const float*)d_in[5];
    const float* bv = (const float*)d_in[6];
    const void*  sl = (const void*)d_in[7];
    float* out = (float*)d_out;

    static bool attr_set = false;
    if (!attr_set) {
        cudaFuncSetAttribute(colsum_wmma, cudaFuncAttributeMaxDynamicSharedMemorySize,
                             SM1_FLOATS * (int)sizeof(float));
        cudaFuncSetAttribute(out_wmma, cudaFuncAttributeMaxDynamicSharedMemorySize,
                             SM2_FLOATS * (int)sizeof(float));
        attr_set = true;
    }

    dim3 g1(LL / 128, BB);
    kqv_kernel<<<g1, 128>>>(x, Wk, bk, Wq, bq, Wv, bv);

    dim3 g2(NLT, BB);
    colsum_wmma<<<g2, 256, SM1_FLOATS * sizeof(float)>>>(sl);

    dim3 g3(LL / 64, BB);
    prep_kernel<<<g3, 256>>>();

    dim3 g4(NLT, BB);
    out_wmma<<<g4, 256, SM2_FLOATS * sizeof(float)>>>(out, sl);
}

// round 4
// speedup vs baseline: 2.5131x; 1.8197x over previous
#include <cuda_runtime.h>
#include <math.h>
#include <stdint.h>

// Problem constants
#define BB 32
#define CC 64
#define LL 2048
#define DD 50
#define DK 64          // padded feature dim (GEMM1 K-dim)
#define TL 128         // l-tile rows per CTA
#define TM 128         // m-tile
#define NLT (LL/TL)    // 16
#define NMT (LL/TM)    // 16
#define LDQ 68         // smem leading dim for 64-wide tiles (64+4)

// Scratch (device globals — allocation is forbidden)
__device__ float g_K[BB*LL*DK];      // tf32(elu(xWk+bk)), zero-padded d 50..63
__device__ float g_Q[BB*LL*DK];
__device__ float g_V[BB*LL*CC];      // tanh(xWv+bv)
__device__ float g_Vp[BB*LL*CC];     // tf32( V[m][c] * cinv[m] )
__device__ float g_part[NLT*BB*LL];  // per-ltile column partial sums

__device__ __forceinline__ float read_len(const void* p) {
    int i = *(const int*)p;
    if (i > 0 && i < (1 << 24)) return (float)i;
    return __int_as_float(i);
}

__device__ __forceinline__ uint32_t f2tf32(float x) {
    uint32_t u;
    asm("cvt.rna.tf32.f32 %0, %1;" : "=r"(u) : "f"(x));
    return u;
}

// D += A(16x8 tf32, row) * B(8x8 tf32, col); acc fp32
__device__ __forceinline__ void mma8(float* d, const uint32_t* a, uint32_t b0, uint32_t b1) {
    asm volatile("mma.sync.aligned.m16n8k8.row.col.f32.tf32.tf32.f32 "
                 "{%0,%1,%2,%3}, {%4,%5,%6,%7}, {%8,%9}, {%0,%1,%2,%3};"
                 : "+f"(d[0]), "+f"(d[1]), "+f"(d[2]), "+f"(d[3])
                 : "r"(a[0]), "r"(a[1]), "r"(a[2]), "r"(a[3]), "r"(b0), "r"(b1));
}

// ---------------------------------------------------------------------------
// Kernel 1: K/Q/V projections + activations. Coalesced in (smem-staged x) and
// coalesced out (smem-staged results). 128 threads, thread owns one l.
// ---------------------------------------------------------------------------
#define KQ_XS    0                    // x tile [64][132]
#define KQ_ST    (KQ_XS + 64*132)     // result staging [128][68]
#define KQ_WK    (KQ_ST + 128*68)     // WkT [52][64]
#define KQ_WQ    (KQ_WK + 52*64)
#define KQ_WV    (KQ_WQ + 52*64)      // WvT [64][64]
#define KQ_BK    (KQ_WV + 64*64)
#define KQ_BQ    (KQ_BK + 52)
#define KQ_BV    (KQ_BQ + 52)
#define KQ_TOTAL (KQ_BV + 64)

__global__ __launch_bounds__(128) void kqv_kernel(
        const float* __restrict__ x,
        const float* __restrict__ Wk, const float* __restrict__ bk,
        const float* __restrict__ Wq, const float* __restrict__ bq,
        const float* __restrict__ Wv, const float* __restrict__ bv) {
    extern __shared__ float sm[];
    float* xs  = sm + KQ_XS;
    float* st  = sm + KQ_ST;
    float* WkT = sm + KQ_WK;
    float* WqT = sm + KQ_WQ;
    float* WvT = sm + KQ_WV;
    float* bks = sm + KQ_BK;
    float* bqs = sm + KQ_BQ;
    float* bvs = sm + KQ_BV;

    const int tid = threadIdx.x;
    const int b = blockIdx.y;
    const int l0 = blockIdx.x * 128;

    // weights transposed [d][c]; rows 50,51 zero
    for (int idx = tid; idx < 52 * 64; idx += 128) {
        int d = idx >> 6, c = idx & 63;
        WkT[idx] = (d < DD) ? Wk[c * DD + d] : 0.0f;
        WqT[idx] = (d < DD) ? Wq[c * DD + d] : 0.0f;
    }
    for (int idx = tid; idx < 64 * 64; idx += 128) {
        int o = idx >> 6, c = idx & 63;
        WvT[idx] = Wv[c * CC + o];
    }
    if (tid < 52) {
        bks[tid] = (tid < DD) ? bk[tid] : 0.0f;
        bqs[tid] = (tid < DD) ? bq[tid] : 0.0f;
    }
    if (tid < 64) bvs[tid] = bv[tid];

    // stage x tile: rows c (64), cols l (128), fully coalesced
    for (int idx = tid; idx < 64 * 32; idx += 128) {
        int row = idx >> 5, c4 = idx & 31;
        *(float4*)&xs[row * 132 + 4 * c4] =
            *(const float4*)(x + (size_t)b * CC * LL + (size_t)row * LL + l0 + 4 * c4);
    }
    __syncthreads();

    float xr[CC];
#pragma unroll
    for (int c = 0; c < CC; c++) xr[c] = xs[c * 132 + tid];

    // ---- K ----
#pragma unroll
    for (int d4 = 0; d4 < 13; d4++) {
        float a0 = bks[4*d4+0], a1 = bks[4*d4+1], a2 = bks[4*d4+2], a3 = bks[4*d4+3];
#pragma unroll
        for (int c = 0; c < CC; c++) {
            float xv = xr[c];
            a0 = fmaf(xv, WkT[(4*d4+0)*64 + c], a0);
            a1 = fmaf(xv, WkT[(4*d4+1)*64 + c], a1);
            a2 = fmaf(xv, WkT[(4*d4+2)*64 + c], a2);
            a3 = fmaf(xv, WkT[(4*d4+3)*64 + c], a3);
        }
        float4 o;
        o.x = __uint_as_float(f2tf32((a0 > 0.f) ? a0 : expm1f(a0)));
        o.y = __uint_as_float(f2tf32((a1 > 0.f) ? a1 : expm1f(a1)));
        o.z = __uint_as_float(f2tf32((a2 > 0.f) ? a2 : expm1f(a2)));
        o.w = __uint_as_float(f2tf32((a3 > 0.f) ? a3 : expm1f(a3)));
        if (d4 == 12) { o.z = 0.0f; o.w = 0.0f; }   // d=50,51 -> 0
        *(float4*)&st[tid * LDQ + 4 * d4] = o;
    }
    __syncthreads();
    for (int idx = tid; idx < 128 * 16; idx += 128) {
        int row = idx >> 4, c4 = idx & 15;
        float4 v = (c4 < 13) ? *(float4*)&st[row * LDQ + 4 * c4]
                             : make_float4(0.f, 0.f, 0.f, 0.f);
        *(float4*)(g_K + ((size_t)b * LL + l0 + row) * DK + 4 * c4) = v;
    }
    __syncthreads();

    // ---- Q ----
#pragma unroll
    for (int d4 = 0; d4 < 13; d4++) {
        float a0 = bqs[4*d4+0], a1 = bqs[4*d4+1], a2 = bqs[4*d4+2], a3 = bqs[4*d4+3];
#pragma unroll
        for (int c = 0; c < CC; c++) {
            float xv = xr[c];
            a0 = fmaf(xv, WqT[(4*d4+0)*64 + c], a0);
            a1 = fmaf(xv, WqT[(4*d4+1)*64 + c], a1);
            a2 = fmaf(xv, WqT[(4*d4+2)*64 + c], a2);
            a3 = fmaf(xv, WqT[(4*d4+3)*64 + c], a3);
        }
        float4 o;
        o.x = __uint_as_float(f2tf32((a0 > 0.f) ? a0 : expm1f(a0)));
        o.y = __uint_as_float(f2tf32((a1 > 0.f) ? a1 : expm1f(a1)));
        o.z = __uint_as_float(f2tf32((a2 > 0.f) ? a2 : expm1f(a2)));
        o.w = __uint_as_float(f2tf32((a3 > 0.f) ? a3 : expm1f(a3)));
        if (d4 == 12) { o.z = 0.0f; o.w = 0.0f; }
        *(float4*)&st[tid * LDQ + 4 * d4] = o;
    }
    __syncthreads();
    for (int idx = tid; idx < 128 * 16; idx += 128) {
        int row = idx >> 4, c4 = idx & 15;
        float4 v = (c4 < 13) ? *(float4*)&st[row * LDQ + 4 * c4]
                             : make_float4(0.f, 0.f, 0.f, 0.f);
        *(float4*)(g_Q + ((size_t)b * LL + l0 + row) * DK + 4 * c4) = v;
    }
    __syncthreads();

    // ---- V ----
#pragma unroll
    for (int d4 = 0; d4 < 16; d4++) {
        float a0 = bvs[4*d4+0], a1 = bvs[4*d4+1], a2 = bvs[4*d4+2], a3 = bvs[4*d4+3];
#pragma unroll
        for (int c = 0; c < CC; c++) {
            float xv = xr[c];
            a0 = fmaf(xv, WvT[(4*d4+0)*64 + c], a0);
            a1 = fmaf(xv, WvT[(4*d4+1)*64 + c], a1);
            a2 = fmaf(xv, WvT[(4*d4+2)*64 + c], a2);
            a3 = fmaf(xv, WvT[(4*d4+3)*64 + c], a3);
        }
        float4 o = make_float4(tanhf(a0), tanhf(a1), tanhf(a2), tanhf(a3));
        *(float4*)&st[tid * LDQ + 4 * d4] = o;
    }
    __syncthreads();
    for (int idx = tid; idx < 128 * 16; idx += 128) {
        int row = idx >> 4, c4 = idx & 15;
        *(float4*)(g_V + ((size_t)b * LL + l0 + row) * CC + 4 * c4) =
            *(float4*)&st[row * LDQ + 4 * c4];
    }
}

// ---------------------------------------------------------------------------
// Kernel 2: column partial sums. 256 threads (8 warps, warp = 16 l-rows).
// S tiles via mma.m16n8k8; exp + in-register column reduce (shfl butterfly).
// ---------------------------------------------------------------------------
#define CS_QS 0
#define CS_RED (CS_QS + 128*LDQ)
#define CS_TOTAL (CS_RED + 8*128)

__global__ __launch_bounds__(256, 3) void colsum_mma(const void* __restrict__ slp) {
    extern __shared__ float sm[];
    float* Qs  = sm + CS_QS;     // [128 m][68 d]
    float* red = sm + CS_RED;    // [8][128]

    const int tid = threadIdx.x;
    const int lane = tid & 31;
    const int wid = tid >> 5;
    const int g = lane >> 2, q = lane & 3;
    const int b = blockIdx.y;
    const int l0 = blockIdx.x * TL;
    const int r0 = wid * 16;
    const float scale = rsqrtf(read_len(slp));

    // K A-fragments cached for whole kernel
    uint32_t Ka[8][4];
    {
        const float* Kb = g_K + ((size_t)b * LL + l0 + r0) * DK;
#pragma unroll
        for (int ks = 0; ks < 8; ks++) {
            int d0 = 8 * ks + q;
            Ka[ks][0] = __float_as_uint(Kb[(size_t)g * DK + d0]);
            Ka[ks][1] = __float_as_uint(Kb[(size_t)(g + 8) * DK + d0]);
            Ka[ks][2] = __float_as_uint(Kb[(size_t)g * DK + d0 + 4]);
            Ka[ks][3] = __float_as_uint(Kb[(size_t)(g + 8) * DK + d0 + 4]);
        }
    }

    for (int mt = 0; mt < NMT; mt++) {
        const int m0 = mt * TM;
        for (int idx = tid; idx < 128 * 16; idx += 256) {
            int row = idx >> 4, c4 = idx & 15;
            *(float4*)&Qs[row * LDQ + 4 * c4] =
                *(const float4*)(g_Q + ((size_t)b * LL + m0 + row) * DK + 4 * c4);
        }
        __syncthreads();

#pragma unroll
        for (int j = 0; j < 16; j++) {
            float acc[4] = {0.f, 0.f, 0.f, 0.f};
#pragma unroll
            for (int ks = 0; ks < 8; ks++) {
                uint32_t b0 = __float_as_uint(Qs[(8 * j + g) * LDQ + 8 * ks + q]);
                uint32_t b1 = __float_as_uint(Qs[(8 * j + g) * LDQ + 8 * ks + q + 4]);
                mma8(acc, Ka[ks], b0, b1);
            }
            float e0 = __expf(acc[0] * scale);
            float e1 = __expf(acc[1] * scale);
            float e2 = __expf(acc[2] * scale);
            float e3 = __expf(acc[3] * scale);
            float s0 = e0 + e2;   // col 8j+2q, rows g,g+8
            float s1 = e1 + e3;   // col 8j+2q+1
#pragma unroll
            for (int off = 4; off < 32; off <<= 1) {
                s0 += __shfl_xor_sync(0xFFFFFFFFu, s0, off);
                s1 += __shfl_xor_sync(0xFFFFFFFFu, s1, off);
            }
            if (lane < 4) {
                red[wid * 128 + 8 * j + 2 * q]     = s0;
                red[wid * 128 + 8 * j + 2 * q + 1] = s1;
            }
        }
        __syncthreads();
        if (tid < 128) {
            float s = 0.f;
#pragma unroll
            for (int w = 0; w < 8; w++) s += red[w * 128 + tid];
            g_part[((size_t)blockIdx.x * BB + b) * LL + m0 + tid] = s;
        }
        __syncthreads();
    }
}

// ---------------------------------------------------------------------------
// Kernel 3: cinv + V' = tf32(V * cinv) (same layout). grid (LL/64, BB), 256 thr.
// ---------------------------------------------------------------------------
__global__ void prep_kernel() {
    __shared__ float ci[64];
    const int tid = threadIdx.x;
    const int b = blockIdx.y;
    const int m0 = blockIdx.x * 64;

    if (tid < 64) {
        float s = 0.0f;
#pragma unroll
        for (int lt = 0; lt < NLT; lt++)
            s += g_part[((size_t)lt * BB + b) * LL + m0 + tid];
        ci[tid] = 1.0f / s;
    }
    __syncthreads();
    for (int idx = tid; idx < 64 * 16; idx += 256) {
        int row = idx >> 4, c4 = idx & 15;
        float cv = ci[row];
        float4 v = *(const float4*)(g_V + ((size_t)b * LL + m0 + row) * CC + 4 * c4);
        float4 o;
        o.x = __uint_as_float(f2tf32(v.x * cv));
        o.y = __uint_as_float(f2tf32(v.y * cv));
        o.z = __uint_as_float(f2tf32(v.z * cv));
        o.w = __uint_as_float(f2tf32(v.w * cv));
        *(float4*)(g_Vp + ((size_t)b * LL + m0 + row) * CC + 4 * c4) = o;
    }
}

// ---------------------------------------------------------------------------
// Kernel 4: Y = P @ V'. 256 threads (8 warps x 16 rows). Per m-tile:
// GEMM1 in 4-col-tile chunks -> exp -> shfl-permute C->A frags -> GEMM2,
// no P SMEM round-trip. Y persists in registers.
// ---------------------------------------------------------------------------
#define OU_QS 0
#define OU_VS (OU_QS + 128*LDQ)
#define OU_TOTAL (OU_VS + 128*LDQ)

__global__ __launch_bounds__(256, 2) void out_mma(float* __restrict__ out,
                                                  const void* __restrict__ slp) {
    extern __shared__ float sm[];
    float* Qs = sm + OU_QS;   // [128 m][68 d]
    float* Vs = sm + OU_VS;   // [128 m][68 c]

    const int tid = threadIdx.x;
    const int lane = tid & 31;
    const int wid = tid >> 5;
    const int g = lane >> 2, q = lane & 3;
    const int b = blockIdx.y;
    const int l0 = blockIdx.x * TL;
    const int r0 = wid * 16;
    const float scale = rsqrtf(read_len(slp));

    const int srcA = (lane & 28) | (q >> 1);
    const int srcB = srcA + 2;
    const bool odd = (q & 1);

    uint32_t Ka[8][4];
    {
        const float* Kb = g_K + ((size_t)b * LL + l0 + r0) * DK;
#pragma unroll
        for (int ks = 0; ks < 8; ks++) {
            int d0 = 8 * ks + q;
            Ka[ks][0] = __float_as_uint(Kb[(size_t)g * DK + d0]);
            Ka[ks][1] = __float_as_uint(Kb[(size_t)(g + 8) * DK + d0]);
            Ka[ks][2] = __float_as_uint(Kb[(size_t)g * DK + d0 + 4]);
            Ka[ks][3] = __float_as_uint(Kb[(size_t)(g + 8) * DK + d0 + 4]);
        }
    }

    float yacc[8][4];
#pragma unroll
    for (int n = 0; n < 8; n++)
#pragma unroll
        for (int e = 0; e < 4; e++) yacc[n][e] = 0.0f;

    for (int mt = 0; mt < NMT; mt++) {
        const int m0 = mt * TM;
        for (int idx = tid; idx < 128 * 16; idx += 256) {
            int row = idx >> 4, c4 = idx & 15;
            *(float4*)&Qs[row * LDQ + 4 * c4] =
                *(const float4*)(g_Q + ((size_t)b * LL + m0 + row) * DK + 4 * c4);
            *(float4*)&Vs[row * LDQ + 4 * c4] =
                *(const float4*)(g_Vp + ((size_t)b * LL + m0 + row) * CC + 4 * c4);
        }
        __syncthreads();

#pragma unroll
        for (int ch = 0; ch < 4; ch++) {
            // GEMM1 chunk: S col-tiles j = 4ch..4ch+3
            float acc[4][4];
#pragma unroll
            for (int jj = 0; jj < 4; jj++)
#pragma unroll
                for (int e = 0; e < 4; e++) acc[jj][e] = 0.0f;

#pragma unroll
            for (int ks = 0; ks < 8; ks++) {
#pragma unroll
                for (int jj = 0; jj < 4; jj++) {
                    int j = 4 * ch + jj;
                    uint32_t b0 = __float_as_uint(Qs[(8 * j + g) * LDQ + 8 * ks + q]);
                    uint32_t b1 = __float_as_uint(Qs[(8 * j + g) * LDQ + 8 * ks + q + 4]);
                    mma8(acc[jj], Ka[ks], b0, b1);
                }
            }

            // exp -> tf32 -> permute C-layout to A-layout
            uint32_t av[4][4];
#pragma unroll
            for (int jj = 0; jj < 4; jj++) {
                uint32_t c0 = f2tf32(__expf(acc[jj][0] * scale));
                uint32_t c1 = f2tf32(__expf(acc[jj][1] * scale));
                uint32_t c2 = f2tf32(__expf(acc[jj][2] * scale));
                uint32_t c3 = f2tf32(__expf(acc[jj][3] * scale));
                uint32_t A0 = __shfl_sync(0xFFFFFFFFu, c0, srcA);
                uint32_t A1 = __shfl_sync(0xFFFFFFFFu, c1, srcA);
                uint32_t A2 = __shfl_sync(0xFFFFFFFFu, c2, srcA);
                uint32_t A3 = __shfl_sync(0xFFFFFFFFu, c3, srcA);
                uint32_t B0 = __shfl_sync(0xFFFFFFFFu, c0, srcB);
                uint32_t B1 = __shfl_sync(0xFFFFFFFFu, c1, srcB);
                uint32_t B2 = __shfl_sync(0xFFFFFFFFu, c2, srcB);
                uint32_t B3 = __shfl_sync(0xFFFFFFFFu, c3, srcB);
                av[jj][0] = odd ? A1 : A0;   // (g,   q)
                av[jj][1] = odd ? A3 : A2;   // (g+8, q)
                av[jj][2] = odd ? B1 : B0;   // (g,   q+4)
                av[jj][3] = odd ? B3 : B2;   // (g+8, q+4)
            }

            // GEMM2 partial: k-steps 4ch+jj over all 8 c-tiles
#pragma unroll
            for (int jj = 0; jj < 4; jj++) {
                int k0 = 8 * (4 * ch + jj);
#pragma unroll
                for (int n = 0; n < 8; n++) {
                    uint32_t b0 = __float_as_uint(Vs[(k0 + q) * LDQ + 8 * n + g]);
                    uint32_t b1 = __float_as_uint(Vs[(k0 + q + 4) * LDQ + 8 * n + g]);
                    mma8(yacc[n], av[jj], b0, b1);
                }
            }
        }
        __syncthreads();
    }

    // store Y from fragments: rows r0+g, r0+g+8; cols 8n+2q, +1
    float* ob = out + ((size_t)b * LL + l0 + r0) * CC;
#pragma unroll
    for (int n = 0; n < 8; n++) {
        *(float2*)&ob[(size_t)g * CC + 8 * n + 2 * q]       = make_float2(yacc[n][0], yacc[n][1]);
        *(float2*)&ob[(size_t)(g + 8) * CC + 8 * n + 2 * q] = make_float2(yacc[n][2], yacc[n][3]);
    }
}

// ---------------------------------------------------------------------------
extern "C" void kernel_launch(void* const* d_in, const int* in_sizes, int n_in,
                              void* d_out, int out_size) {
    const float* x  = (const float*)d_in[0];
    const float* Wk = (const float*)d_in[1];
    const float* bk = (const float*)d_in[2];
    const float* Wq = (const float*)d_in[3];
    const float* bq = (const float*)d_in[4];
    const float* Wv = (const float*)d_in[5];
    const float* bv = (const float*)d_in[6];
    const void*  sl = (const void*)d_in[7];
    float* out = (float*)d_out;

    static bool attr_set = false;
    if (!attr_set) {
        cudaFuncSetAttribute(kqv_kernel, cudaFuncAttributeMaxDynamicSharedMemorySize,
                             KQ_TOTAL * (int)sizeof(float));
        cudaFuncSetAttribute(colsum_mma, cudaFuncAttributeMaxDynamicSharedMemorySize,
                             CS_TOTAL * (int)sizeof(float));
        cudaFuncSetAttribute(out_mma, cudaFuncAttributeMaxDynamicSharedMemorySize,
                             OU_TOTAL * (int)sizeof(float));
        attr_set = true;
    }

    dim3 g1(LL / 128, BB);
    kqv_kernel<<<g1, 128, KQ_TOTAL * sizeof(float)>>>(x, Wk, bk, Wq, bq, Wv, bv);

    dim3 g2(NLT, BB);
    colsum_mma<<<g2, 256, CS_TOTAL * sizeof(float)>>>(sl);

    dim3 g3(LL / 64, BB);
    prep_kernel<<<g3, 256>>>();

    dim3 g4(NLT, BB);
    out_mma<<<g4, 256, OU_TOTAL * sizeof(float)>>>(out, sl);
}

// round 5
// speedup vs baseline: 3.1810x; 1.2658x over previous
#include <cuda_runtime.h>
#include <cuda_fp16.h>
#include <math.h>
#include <stdint.h>

// Problem constants
#define BB 32
#define CC 64
#define LL 2048
#define DD 50
#define DK 64          // padded feature dim (GEMM1 K-dim)
#define TL 128         // l-tile rows per CTA
#define TM 128         // m-tile
#define NLT (LL/TL)    // 16
#define NMT (LL/TM)    // 16
#define LDQ 72         // smem leading dim (floats) for K/Q tiles: 72 ≡ 8 (mod 32) -> conflict-free LDS.64
#define LDVH 144       // smem leading dim (halves) for V' tile: 144h = 72 words -> same property
#define LDST 68        // kqv staging ld

// Scratch (device globals — allocation is forbidden)
// g_K/g_Q: tf32 values, d-INTERLEAVED: pos(d) = (d&~7) + 2*(d&3) + ((d>>2)&1).
// g_K additionally pre-scaled by 1/sqrt(sample_len).
__device__ float g_K[BB*LL*DK];
__device__ float g_Q[BB*LL*DK];
__device__ float g_V[BB*LL*CC];        // tanh(xWv+bv), plain [m][c]
// V' = V[m][c]*cinv[m], fp16, layout [b][c][m'] with m' = perm16(m):
// perm16(m) = (m&~15) + 4*((m>>1)&3) + 2*((m>>3)&1) + (m&1)
__device__ __half g_Vph[BB*CC*LL];
__device__ float g_part[NLT*BB*LL];    // per-ltile column partial sums

__device__ __forceinline__ float read_len(const void* p) {
    int i = *(const int*)p;
    if (i > 0 && i < (1 << 24)) return (float)i;
    return __int_as_float(i);
}

__device__ __forceinline__ uint32_t f2tf32(float x) {
    uint32_t u;
    asm("cvt.rna.tf32.f32 %0, %1;" : "=r"(u) : "f"(x));
    return u;
}

__device__ __forceinline__ uint32_t packh2(float lo, float hi) {
    __half2 h = __floats2half2_rn(lo, hi);
    return *(uint32_t*)&h;
}

// D += A(16x8 tf32, row) * B(8x8 tf32, col); fp32 acc
__device__ __forceinline__ void mma8(float* d, const uint32_t* a, uint32_t b0, uint32_t b1) {
    asm volatile("mma.sync.aligned.m16n8k8.row.col.f32.tf32.tf32.f32 "
                 "{%0,%1,%2,%3}, {%4,%5,%6,%7}, {%8,%9}, {%0,%1,%2,%3};"
                 : "+f"(d[0]), "+f"(d[1]), "+f"(d[2]), "+f"(d[3])
                 : "r"(a[0]), "r"(a[1]), "r"(a[2]), "r"(a[3]), "r"(b0), "r"(b1));
}

// D += A(16x16 f16, row) * B(16x8 f16, col); fp32 acc
__device__ __forceinline__ void mma16(float* d, uint32_t a0, uint32_t a1, uint32_t a2,
                                      uint32_t a3, uint32_t b0, uint32_t b1) {
    asm volatile("mma.sync.aligned.m16n8k16.row.col.f32.f16.f16.f32 "
                 "{%0,%1,%2,%3}, {%4,%5,%6,%7}, {%8,%9}, {%0,%1,%2,%3};"
                 : "+f"(d[0]), "+f"(d[1]), "+f"(d[2]), "+f"(d[3])
                 : "r"(a0), "r"(a1), "r"(a2), "r"(a3), "r"(b0), "r"(b1));
}

// ---------------------------------------------------------------------------
// Kernel 1: K/Q/V projections + activations.
// K gets scale folded in; K/Q written d-interleaved + tf32-rounded.
// ---------------------------------------------------------------------------
#define KQ_XS    0                    // x tile [64][132]
#define KQ_ST    (KQ_XS + 64*132)     // staging [128][68]
#define KQ_WK    (KQ_ST + 128*LDST)
#define KQ_WQ    (KQ_WK + 52*64)
#define KQ_WV    (KQ_WQ + 52*64)
#define KQ_BK    (KQ_WV + 64*64)
#define KQ_BQ    (KQ_BK + 52)
#define KQ_BV    (KQ_BQ + 52)
#define KQ_TOTAL (KQ_BV + 64)

__global__ __launch_bounds__(128) void kqv_kernel(
        const float* __restrict__ x,
        const float* __restrict__ Wk, const float* __restrict__ bk,
        const float* __restrict__ Wq, const float* __restrict__ bq,
        const float* __restrict__ Wv, const float* __restrict__ bv,
        const void* __restrict__ slp) {
    extern __shared__ float sm[];
    float* xs  = sm + KQ_XS;
    float* st  = sm + KQ_ST;
    float* WkT = sm + KQ_WK;
    float* WqT = sm + KQ_WQ;
    float* WvT = sm + KQ_WV;
    float* bks = sm + KQ_BK;
    float* bqs = sm + KQ_BQ;
    float* bvs = sm + KQ_BV;

    const int tid = threadIdx.x;
    const int b = blockIdx.y;
    const int l0 = blockIdx.x * 128;
    const float scale = rsqrtf(read_len(slp));

    for (int idx = tid; idx < 52 * 64; idx += 128) {
        int d = idx >> 6, c = idx & 63;
        WkT[idx] = (d < DD) ? Wk[c * DD + d] : 0.0f;
        WqT[idx] = (d < DD) ? Wq[c * DD + d] : 0.0f;
    }
    for (int idx = tid; idx < 64 * 64; idx += 128) {
        int o = idx >> 6, c = idx & 63;
        WvT[idx] = Wv[c * CC + o];
    }
    if (tid < 52) {
        bks[tid] = (tid < DD) ? bk[tid] : 0.0f;
        bqs[tid] = (tid < DD) ? bq[tid] : 0.0f;
    }
    if (tid < 64) bvs[tid] = bv[tid];

    for (int idx = tid; idx < 64 * 32; idx += 128) {
        int row = idx >> 5, c4 = idx & 31;
        *(float4*)&xs[row * 132 + 4 * c4] =
            *(const float4*)(x + (size_t)b * CC * LL + (size_t)row * LL + l0 + 4 * c4);
    }
    __syncthreads();

    float xr[CC];
#pragma unroll
    for (int c = 0; c < CC; c++) xr[c] = xs[c * 132 + tid];

    // ---- K (scaled) ----
#pragma unroll
    for (int d4 = 0; d4 < 13; d4++) {
        float a0 = bks[4*d4+0], a1 = bks[4*d4+1], a2 = bks[4*d4+2], a3 = bks[4*d4+3];
#pragma unroll
        for (int c = 0; c < CC; c++) {
            float xv = xr[c];
            a0 = fmaf(xv, WkT[(4*d4+0)*64 + c], a0);
            a1 = fmaf(xv, WkT[(4*d4+1)*64 + c], a1);
            a2 = fmaf(xv, WkT[(4*d4+2)*64 + c], a2);
            a3 = fmaf(xv, WkT[(4*d4+3)*64 + c], a3);
        }
        float4 o;
        o.x = __uint_as_float(f2tf32(scale * ((a0 > 0.f) ? a0 : expm1f(a0))));
        o.y = __uint_as_float(f2tf32(scale * ((a1 > 0.f) ? a1 : expm1f(a1))));
        o.z = __uint_as_float(f2tf32(scale * ((a2 > 0.f) ? a2 : expm1f(a2))));
        o.w = __uint_as_float(f2tf32(scale * ((a3 > 0.f) ? a3 : expm1f(a3))));
        if (d4 == 12) { o.z = 0.0f; o.w = 0.0f; }   // d=50,51
        *(float4*)&st[tid * LDST + 4 * d4] = o;
    }
    __syncthreads();
    // write permuted: pos p even pair (h=0,1) -> source d0 = (p&~7)+((p>>1)&3), d1 = d0+4
    for (int idx = tid; idx < 128 * 32; idx += 128) {
        int row = idx >> 5, pp = idx & 31;
        int p = 2 * pp;
        int d0 = (p & ~7) + ((p >> 1) & 3);
        int d1 = d0 + 4;
        float2 o;
        o.x = (d0 < 52) ? st[row * LDST + d0] : 0.0f;
        o.y = (d1 < 52) ? st[row * LDST + d1] : 0.0f;
        *(float2*)(g_K + ((size_t)b * LL + l0 + row) * DK + p) = o;
    }
    __syncthreads();

    // ---- Q ----
#pragma unroll
    for (int d4 = 0; d4 < 13; d4++) {
        float a0 = bqs[4*d4+0], a1 = bqs[4*d4+1], a2 = bqs[4*d4+2], a3 = bqs[4*d4+3];
#pragma unroll
        for (int c = 0; c < CC; c++) {
            float xv = xr[c];
            a0 = fmaf(xv, WqT[(4*d4+0)*64 + c], a0);
            a1 = fmaf(xv, WqT[(4*d4+1)*64 + c], a1);
            a2 = fmaf(xv, WqT[(4*d4+2)*64 + c], a2);
            a3 = fmaf(xv, WqT[(4*d4+3)*64 + c], a3);
        }
        float4 o;
        o.x = __uint_as_float(f2tf32((a0 > 0.f) ? a0 : expm1f(a0)));
        o.y = __uint_as_float(f2tf32((a1 > 0.f) ? a1 : expm1f(a1)));
        o.z = __uint_as_float(f2tf32((a2 > 0.f) ? a2 : expm1f(a2)));
        o.w = __uint_as_float(f2tf32((a3 > 0.f) ? a3 : expm1f(a3)));
        if (d4 == 12) { o.z = 0.0f; o.w = 0.0f; }
        *(float4*)&st[tid * LDST + 4 * d4] = o;
    }
    __syncthreads();
    for (int idx = tid; idx < 128 * 32; idx += 128) {
        int row = idx >> 5, pp = idx & 31;
        int p = 2 * pp;
        int d0 = (p & ~7) + ((p >> 1) & 3);
        int d1 = d0 + 4;
        float2 o;
        o.x = (d0 < 52) ? st[row * LDST + d0] : 0.0f;
        o.y = (d1 < 52) ? st[row * LDST + d1] : 0.0f;
        *(float2*)(g_Q + ((size_t)b * LL + l0 + row) * DK + p) = o;
    }
    __syncthreads();

    // ---- V ----
#pragma unroll
    for (int d4 = 0; d4 < 16; d4++) {
        float a0 = bvs[4*d4+0], a1 = bvs[4*d4+1], a2 = bvs[4*d4+2], a3 = bvs[4*d4+3];
#pragma unroll
        for (int c = 0; c < CC; c++) {
            float xv = xr[c];
            a0 = fmaf(xv, WvT[(4*d4+0)*64 + c], a0);
            a1 = fmaf(xv, WvT[(4*d4+1)*64 + c], a1);
            a2 = fmaf(xv, WvT[(4*d4+2)*64 + c], a2);
            a3 = fmaf(xv, WvT[(4*d4+3)*64 + c], a3);
        }
        float4 o = make_float4(tanhf(a0), tanhf(a1), tanhf(a2), tanhf(a3));
        *(float4*)&st[tid * LDST + 4 * d4] = o;
    }
    __syncthreads();
    for (int idx = tid; idx < 128 * 16; idx += 128) {
        int row = idx >> 4, c4 = idx & 15;
        *(float4*)(g_V + ((size_t)b * LL + l0 + row) * CC + 4 * c4) =
            *(float4*)&st[row * LDST + 4 * c4];
    }
}

// ---------------------------------------------------------------------------
// Kernel 2: column partial sums. 256 threads (8 warps x 16 rows).
// Vectorized LDS.64 B-fragment loads; scale pre-folded into K.
// ---------------------------------------------------------------------------
#define CS_QS 0
#define CS_RED (CS_QS + 128*LDQ)
#define CS_TOTAL (CS_RED + 8*128)

__global__ __launch_bounds__(256, 3) void colsum_mma() {
    extern __shared__ float sm[];
    float* Qs  = sm + CS_QS;     // [128 m][72]
    float* red = sm + CS_RED;    // [8][128]

    const int tid = threadIdx.x;
    const int lane = tid & 31;
    const int wid = tid >> 5;
    const int g = lane >> 2, q = lane & 3;
    const int b = blockIdx.y;
    const int l0 = blockIdx.x * TL;
    const int r0 = wid * 16;

    uint32_t Ka[8][4];
    {
        const float* Kb = g_K + ((size_t)b * LL + l0 + r0) * DK;
#pragma unroll
        for (int ks = 0; ks < 8; ks++) {
            float2 lo = *(const float2*)&Kb[(size_t)g * DK + 8 * ks + 2 * q];
            float2 hi = *(const float2*)&Kb[(size_t)(g + 8) * DK + 8 * ks + 2 * q];
            Ka[ks][0] = __float_as_uint(lo.x);
            Ka[ks][1] = __float_as_uint(hi.x);
            Ka[ks][2] = __float_as_uint(lo.y);
            Ka[ks][3] = __float_as_uint(hi.y);
        }
    }

    for (int mt = 0; mt < NMT; mt++) {
        const int m0 = mt * TM;
        for (int idx = tid; idx < 128 * 16; idx += 256) {
            int row = idx >> 4, c4 = idx & 15;
            *(float4*)&Qs[row * LDQ + 4 * c4] =
                *(const float4*)(g_Q + ((size_t)b * LL + m0 + row) * DK + 4 * c4);
        }
        __syncthreads();

#pragma unroll
        for (int j = 0; j < 16; j++) {
            float acc[4] = {0.f, 0.f, 0.f, 0.f};
#pragma unroll
            for (int ks = 0; ks < 8; ks++) {
                float2 bb = *(const float2*)&Qs[(8 * j + g) * LDQ + 8 * ks + 2 * q];
                mma8(acc, Ka[ks], __float_as_uint(bb.x), __float_as_uint(bb.y));
            }
            float s0 = __expf(acc[0]) + __expf(acc[2]);   // col 8j+2q
            float s1 = __expf(acc[1]) + __expf(acc[3]);   // col 8j+2q+1
#pragma unroll
            for (int off = 4; off < 32; off <<= 1) {
                s0 += __shfl_xor_sync(0xFFFFFFFFu, s0, off);
                s1 += __shfl_xor_sync(0xFFFFFFFFu, s1, off);
            }
            if (lane < 4) {
                red[wid * 128 + 8 * j + 2 * q]     = s0;
                red[wid * 128 + 8 * j + 2 * q + 1] = s1;
            }
        }
        __syncthreads();
        if (tid < 128) {
            float s = 0.f;
#pragma unroll
            for (int w = 0; w < 8; w++) s += red[w * 128 + tid];
            g_part[((size_t)blockIdx.x * BB + b) * LL + m0 + tid] = s;
        }
        __syncthreads();
    }
}

// ---------------------------------------------------------------------------
// Kernel 3: cinv; V' = fp16(V*cinv) transposed [c][m'] with perm16 interleave.
// grid (LL/64, BB), 256 threads.
// ---------------------------------------------------------------------------
__global__ void prep_kernel() {
    __shared__ float ci[64];
    __shared__ float vt[64 * 68];
    const int tid = threadIdx.x;
    const int b = blockIdx.y;
    const int m0 = blockIdx.x * 64;

    if (tid < 64) {
        float s = 0.0f;
#pragma unroll
        for (int lt = 0; lt < NLT; lt++)
            s += g_part[((size_t)lt * BB + b) * LL + m0 + tid];
        ci[tid] = 1.0f / s;
    }
    for (int idx = tid; idx < 64 * 16; idx += 256) {
        int row = idx >> 4, c4 = idx & 15;
        *(float4*)&vt[row * 68 + 4 * c4] =
            *(const float4*)(g_V + ((size_t)b * LL + m0 + row) * CC + 4 * c4);
    }
    __syncthreads();
    // write pairs: even position p=2*jp covers source rows (m, m+1)
    for (int idx = tid; idx < 64 * 32; idx += 256) {
        int c = idx >> 5, jp = idx & 31;
        int m = 16 * (jp >> 3) + 8 * (jp & 1) + 2 * ((jp >> 1) & 3);
        __half2 hv = __floats2half2_rn(vt[m * 68 + c] * ci[m],
                                       vt[(m + 1) * 68 + c] * ci[m + 1]);
        *(__half2*)(g_Vph + ((size_t)b * CC + c) * LL + m0 + 2 * jp) = hv;
    }
}

// ---------------------------------------------------------------------------
// Kernel 4: Y = P @ V'. GEMM1 tf32 -> exp -> cvt.f16x2 (no shuffles!) ->
// GEMM2 fp16 m16n8k16 with LDS.64 B-frags. 256 threads, 8 warps x 16 rows.
// ---------------------------------------------------------------------------
#define OU_QS 0
#define OU_VH (OU_QS + 128*LDQ)              // float offset; Vhs = halves
#define OU_TOTAL (OU_VH + (64*LDVH)/2)       // in floats

__global__ __launch_bounds__(256, 2) void out_mma(float* __restrict__ out) {
    extern __shared__ float sm[];
    float* Qs = sm + OU_QS;                  // [128 m][72]
    __half* Vhs = (__half*)(sm + OU_VH);     // [64 c][144 m'-halves]

    const int tid = threadIdx.x;
    const int lane = tid & 31;
    const int wid = tid >> 5;
    const int g = lane >> 2, q = lane & 3;
    const int b = blockIdx.y;
    const int l0 = blockIdx.x * TL;
    const int r0 = wid * 16;

    uint32_t Ka[8][4];
    {
        const float* Kb = g_K + ((size_t)b * LL + l0 + r0) * DK;
#pragma unroll
        for (int ks = 0; ks < 8; ks++) {
            float2 lo = *(const float2*)&Kb[(size_t)g * DK + 8 * ks + 2 * q];
            float2 hi = *(const float2*)&Kb[(size_t)(g + 8) * DK + 8 * ks + 2 * q];
            Ka[ks][0] = __float_as_uint(lo.x);
            Ka[ks][1] = __float_as_uint(hi.x);
            Ka[ks][2] = __float_as_uint(lo.y);
            Ka[ks][3] = __float_as_uint(hi.y);
        }
    }

    float yacc[8][4];
#pragma unroll
    for (int n = 0; n < 8; n++)
#pragma unroll
        for (int e = 0; e < 4; e++) yacc[n][e] = 0.0f;

    for (int mt = 0; mt < NMT; mt++) {
        const int m0 = mt * TM;
        for (int idx = tid; idx < 128 * 16; idx += 256) {
            int row = idx >> 4, c4 = idx & 15;
            *(float4*)&Qs[row * LDQ + 4 * c4] =
                *(const float4*)(g_Q + ((size_t)b * LL + m0 + row) * DK + 4 * c4);
        }
        for (int idx = tid; idx < 64 * 16; idx += 256) {
            int c = idx >> 4, j16 = idx & 15;
            *(uint4*)&Vhs[c * LDVH + 8 * j16] =
                *(const uint4*)(g_Vph + ((size_t)b * CC + c) * LL + m0 + 8 * j16);
        }
        __syncthreads();

#pragma unroll
        for (int t = 0; t < 8; t++) {
            // GEMM1: S col-tiles j = 2t, 2t+1
            float acc0[4] = {0.f, 0.f, 0.f, 0.f};
            float acc1[4] = {0.f, 0.f, 0.f, 0.f};
#pragma unroll
            for (int ks = 0; ks < 8; ks++) {
                float2 b0 = *(const float2*)&Qs[(16 * t + g) * LDQ + 8 * ks + 2 * q];
                float2 b1 = *(const float2*)&Qs[(16 * t + 8 + g) * LDQ + 8 * ks + 2 * q];
                mma8(acc0, Ka[ks], __float_as_uint(b0.x), __float_as_uint(b0.y));
                mma8(acc1, Ka[ks], __float_as_uint(b1.x), __float_as_uint(b1.y));
            }
            // P fragment: exp then pack f32x2 -> f16x2; C layout == fp16 A layout
            uint32_t a0 = packh2(__expf(acc0[0]), __expf(acc0[1]));
            uint32_t a1 = packh2(__expf(acc0[2]), __expf(acc0[3]));
            uint32_t a2 = packh2(__expf(acc1[0]), __expf(acc1[1]));
            uint32_t a3 = packh2(__expf(acc1[2]), __expf(acc1[3]));

            // GEMM2: Y += P(k-block t) @ V' ; B-frag = one LDS.64
#pragma unroll
            for (int n = 0; n < 8; n++) {
                uint2 bb = *(const uint2*)&Vhs[(8 * n + g) * LDVH + 16 * t + 4 * q];
                mma16(yacc[n], a0, a1, a2, a3, bb.x, bb.y);
            }
        }
        __syncthreads();
    }

    float* ob = out + ((size_t)b * LL + l0 + r0) * CC;
#pragma unroll
    for (int n = 0; n < 8; n++) {
        *(float2*)&ob[(size_t)g * CC + 8 * n + 2 * q]       = make_float2(yacc[n][0], yacc[n][1]);
        *(float2*)&ob[(size_t)(g + 8) * CC + 8 * n + 2 * q] = make_float2(yacc[n][2], yacc[n][3]);
    }
}

// ---------------------------------------------------------------------------
extern "C" void kernel_launch(void* const* d_in, const int* in_sizes, int n_in,
                              void* d_out, int out_size) {
    const float* x  = (const float*)d_in[0];
    const float* Wk = (const float*)d_in[1];
    const float* bk = (const float*)d_in[2];
    const float* Wq = (const float*)d_in[3];
    const float* bq = (const float*)d_in[4];
    const float* Wv = (const float*)d_in[5];
    const float* bv = (const float*)d_in[6];
    const void*  sl = (const void*)d_in[7];
    float* out = (float*)d_out;

    static bool attr_set = false;
    if (!attr_set) {
        cudaFuncSetAttribute(kqv_kernel, cudaFuncAttributeMaxDynamicSharedMemorySize,
                             KQ_TOTAL * (int)sizeof(float));
        cudaFuncSetAttribute(colsum_mma, cudaFuncAttributeMaxDynamicSharedMemorySize,
                             CS_TOTAL * (int)sizeof(float));
        cudaFuncSetAttribute(out_mma, cudaFuncAttributeMaxDynamicSharedMemorySize,
                             OU_TOTAL * (int)sizeof(float));
        attr_set = true;
    }

    dim3 g1(LL / 128, BB);
    kqv_kernel<<<g1, 128, KQ_TOTAL * sizeof(float)>>>(x, Wk, bk, Wq, bq, Wv, bv, sl);

    dim3 g2(NLT, BB);
    colsum_mma<<<g2, 256, CS_TOTAL * sizeof(float)>>>();

    dim3 g3(LL / 64, BB);
    prep_kernel<<<g3, 256>>>();

    dim3 g4(NLT, BB);
    out_mma<<<g4, 256, OU_TOTAL * sizeof(float)>>>(out);
}

// round 6
// speedup vs baseline: 4.9031x; 1.5414x over previous
#include <cuda_runtime.h>
#include <cuda_fp16.h>
#include <math.h>
#include <stdint.h>

// Problem constants
#define BB 32
#define CC 64
#define LL 2048
#define DD 50
#define DK 64
#define TL 128
#define NLT (LL/TL)    // 16
#define NMT (LL/128)   // 16

// Scratch (device globals — allocation is forbidden)
// g_Kh/g_Qh: fp16, d interleaved within 16-chunks: pos 4q..4q+3 hold d = 2q,2q+1,2q+8,2q+9.
// g_Kh pre-scaled by log2e/sqrt(sample_len).
__device__ __half g_Kh[BB*LL*DK];
__device__ __half g_Qh[BB*LL*DK];
__device__ float  g_V[BB*LL*CC];          // tanh(xWv+bv), [m][c] fp32
__device__ __half g_Vph[BB*CC*LL];        // V' = V*cinv, [c][m'] perm16 on m
__device__ __half g_P[BB*LL*LL];          // P = fp16(exp(S)), [l][m'] perm16 on m (268MB)
__device__ float  g_part[NLT*BB*LL];      // per-ltile column partials

__device__ __forceinline__ float read_len(const void* p) {
    int i = *(const int*)p;
    if (i > 0 && i < (1 << 24)) return (float)i;
    return __int_as_float(i);
}
__device__ __forceinline__ uint32_t f2tf32(float x) {
    uint32_t u;
    asm("cvt.rna.tf32.f32 %0, %1;" : "=r"(u) : "f"(x));
    return u;
}
__device__ __forceinline__ uint32_t packh2(float lo, float hi) {
    __half2 h = __floats2half2_rn(lo, hi);
    return *(uint32_t*)&h;
}
// D += A(16x8 tf32) * B(8x8 tf32)
__device__ __forceinline__ void mma8(float* d, const uint32_t* a, uint32_t b0, uint32_t b1) {
    asm volatile("mma.sync.aligned.m16n8k8.row.col.f32.tf32.tf32.f32 "
                 "{%0,%1,%2,%3}, {%4,%5,%6,%7}, {%8,%9}, {%0,%1,%2,%3};"
                 : "+f"(d[0]), "+f"(d[1]), "+f"(d[2]), "+f"(d[3])
                 : "r"(a[0]), "r"(a[1]), "r"(a[2]), "r"(a[3]), "r"(b0), "r"(b1));
}
// D += A(16x16 f16) * B(16x8 f16)
__device__ __forceinline__ void mma16(float* d, uint32_t a0, uint32_t a1, uint32_t a2,
                                      uint32_t a3, uint32_t b0, uint32_t b1) {
    asm volatile("mma.sync.aligned.m16n8k16.row.col.f32.f16.f16.f32 "
                 "{%0,%1,%2,%3}, {%4,%5,%6,%7}, {%8,%9}, {%0,%1,%2,%3};"
                 : "+f"(d[0]), "+f"(d[1]), "+f"(d[2]), "+f"(d[3])
                 : "r"(a0), "r"(a1), "r"(a2), "r"(a3), "r"(b0), "r"(b1));
}

// ---------------------------------------------------------------------------
// Kernel 1: projections via tf32 mma8. grid (16, 32), 256 thr (8 warps x 16 l).
// smem floats: xs[64][136] | Wsm[176][72] (K 0..55, Q 56..111, V 112..175,
// c-interleaved pairs (c, c+4)) | stg[128][72] | bias[176]
// ---------------------------------------------------------------------------
#define KQ_XS   0
#define KQ_WS   (KQ_XS + 64*136)
#define KQ_STG  (KQ_WS + 176*72)
#define KQ_BIA  (KQ_STG + 128*72)
#define KQ_TOT  (KQ_BIA + 176)
#define LDX 136
#define LDW 72

__global__ __launch_bounds__(256) void kqv_mma(
        const float* __restrict__ x,
        const float* __restrict__ Wk, const float* __restrict__ bk,
        const float* __restrict__ Wq, const float* __restrict__ bq,
        const float* __restrict__ Wv, const float* __restrict__ bv,
        const void* __restrict__ slp) {
    extern __shared__ float sm[];
    float* xs   = sm + KQ_XS;
    float* Wsm  = sm + KQ_WS;
    float* stg  = sm + KQ_STG;
    float* bias = sm + KQ_BIA;

    const int tid = threadIdx.x;
    const int lane = tid & 31;
    const int wid = tid >> 5;
    const int g = lane >> 2, q = lane & 3;
    const int b = blockIdx.y;
    const int l0 = blockIdx.x * 128;
    const int r0 = wid * 16;
    const float kscale = rsqrtf(read_len(slp)) * 1.4426950408889634f;

    // Weights, c-interleaved: pos(c) = (c&~7) | ((c&3)<<1) | ((c>>2)&1)
    for (int idx = tid; idx < 56 * 64; idx += 256) {
        int d = idx >> 6, c = idx & 63;
        int pos = (c & ~7) | ((c & 3) << 1) | ((c >> 2) & 1);
        Wsm[d * LDW + pos]        = (d < DD) ? __uint_as_float(f2tf32(Wk[c * DD + d])) : 0.0f;
        Wsm[(56 + d) * LDW + pos] = (d < DD) ? __uint_as_float(f2tf32(Wq[c * DD + d])) : 0.0f;
    }
    for (int idx = tid; idx < 64 * 64; idx += 256) {
        int o = idx >> 6, c = idx & 63;
        int pos = (c & ~7) | ((c & 3) << 1) | ((c >> 2) & 1);
        Wsm[(112 + o) * LDW + pos] = __uint_as_float(f2tf32(Wv[c * CC + o]));
    }
    if (tid < 56)  bias[tid]       = (tid < DD) ? bk[tid] : 0.0f;
    if (tid < 56)  bias[56 + tid]  = (tid < DD) ? bq[tid] : 0.0f;
    if (tid < 64)  bias[112 + tid] = bv[tid];

    for (int idx = tid; idx < 64 * 32; idx += 256) {
        int row = idx >> 5, c4 = idx & 31;
        float4 v = *(const float4*)(x + (size_t)b * CC * LL + (size_t)row * LL + l0 + 4 * c4);
        v.x = __uint_as_float(f2tf32(v.x)); v.y = __uint_as_float(f2tf32(v.y));
        v.z = __uint_as_float(f2tf32(v.z)); v.w = __uint_as_float(f2tf32(v.w));
        *(float4*)&xs[row * LDX + 4 * c4] = v;
    }
    __syncthreads();

    // A fragments (x^T rows = l), cached for all n-tiles
    uint32_t xa[8][4];
#pragma unroll
    for (int ks = 0; ks < 8; ks++) {
        xa[ks][0] = __float_as_uint(xs[(8 * ks + q) * LDX + r0 + g]);
        xa[ks][1] = __float_as_uint(xs[(8 * ks + q) * LDX + r0 + g + 8]);
        xa[ks][2] = __float_as_uint(xs[(8 * ks + q + 4) * LDX + r0 + g]);
        xa[ks][3] = __float_as_uint(xs[(8 * ks + q + 4) * LDX + r0 + g + 8]);
    }

    // ---- phase K (rows 0..6 of Wsm), elu, pack fp16 scaled ----
#pragma unroll
    for (int nt = 0; nt < 7; nt++) {
        float acc[4] = {0.f, 0.f, 0.f, 0.f};
#pragma unroll
        for (int ks = 0; ks < 8; ks++) {
            float2 bb = *(const float2*)&Wsm[(8 * nt + g) * LDW + 8 * ks + 2 * q];
            mma8(acc, xa[ks], __float_as_uint(bb.x), __float_as_uint(bb.y));
        }
        float b0 = bias[8 * nt + 2 * q], b1 = bias[8 * nt + 2 * q + 1];
        float v0 = acc[0] + b0, v1 = acc[1] + b1, v2 = acc[2] + b0, v3 = acc[3] + b1;
        v0 = (v0 > 0.f) ? v0 : expm1f(v0); v1 = (v1 > 0.f) ? v1 : expm1f(v1);
        v2 = (v2 > 0.f) ? v2 : expm1f(v2); v3 = (v3 > 0.f) ? v3 : expm1f(v3);
        *(float2*)&stg[(r0 + g) * LDW + 8 * nt + 2 * q]     = make_float2(v0, v1);
        *(float2*)&stg[(r0 + g + 8) * LDW + 8 * nt + 2 * q] = make_float2(v2, v3);
    }
    for (int idx = tid; idx < 128 * 8; idx += 256)
        stg[(idx >> 3) * LDW + 56 + (idx & 7)] = 0.0f;
    __syncthreads();
    for (int idx = tid; idx < 128 * 32; idx += 256) {
        int row = idx >> 5, p = (idx & 31) * 2;
        int pl = p & 15;
        int d0 = (p & ~15) + 2 * ((pl >> 2) & 3) + 8 * ((pl >> 1) & 1);
        __half2 h = __floats2half2_rn(stg[row * LDW + d0] * kscale,
                                      stg[row * LDW + d0 + 1] * kscale);
        *(__half2*)(g_Kh + ((size_t)b * LL + l0 + row) * DK + p) = h;
    }
    __syncthreads();

    // ---- phase Q (rows 56..), elu, pack fp16 ----
#pragma unroll
    for (int nt = 0; nt < 7; nt++) {
        float acc[4] = {0.f, 0.f, 0.f, 0.f};
#pragma unroll
        for (int ks = 0; ks < 8; ks++) {
            float2 bb = *(const float2*)&Wsm[(56 + 8 * nt + g) * LDW + 8 * ks + 2 * q];
            mma8(acc, xa[ks], __float_as_uint(bb.x), __float_as_uint(bb.y));
        }
        float b0 = bias[56 + 8 * nt + 2 * q], b1 = bias[56 + 8 * nt + 2 * q + 1];
        float v0 = acc[0] + b0, v1 = acc[1] + b1, v2 = acc[2] + b0, v3 = acc[3] + b1;
        v0 = (v0 > 0.f) ? v0 : expm1f(v0); v1 = (v1 > 0.f) ? v1 : expm1f(v1);
        v2 = (v2 > 0.f) ? v2 : expm1f(v2); v3 = (v3 > 0.f) ? v3 : expm1f(v3);
        *(float2*)&stg[(r0 + g) * LDW + 8 * nt + 2 * q]     = make_float2(v0, v1);
        *(float2*)&stg[(r0 + g + 8) * LDW + 8 * nt + 2 * q] = make_float2(v2, v3);
    }
    for (int idx = tid; idx < 128 * 8; idx += 256)
        stg[(idx >> 3) * LDW + 56 + (idx & 7)] = 0.0f;
    __syncthreads();
    for (int idx = tid; idx < 128 * 32; idx += 256) {
        int row = idx >> 5, p = (idx & 31) * 2;
        int pl = p & 15;
        int d0 = (p & ~15) + 2 * ((pl >> 2) & 3) + 8 * ((pl >> 1) & 1);
        __half2 h = __floats2half2_rn(stg[row * LDW + d0], stg[row * LDW + d0 + 1]);
        *(__half2*)(g_Qh + ((size_t)b * LL + l0 + row) * DK + p) = h;
    }
    __syncthreads();

    // ---- phase V (rows 112..), tanh, fp32 plain ----
#pragma unroll
    for (int nt = 0; nt < 8; nt++) {
        float acc[4] = {0.f, 0.f, 0.f, 0.f};
#pragma unroll
        for (int ks = 0; ks < 8; ks++) {
            float2 bb = *(const float2*)&Wsm[(112 + 8 * nt + g) * LDW + 8 * ks + 2 * q];
            mma8(acc, xa[ks], __float_as_uint(bb.x), __float_as_uint(bb.y));
        }
        float b0 = bias[112 + 8 * nt + 2 * q], b1 = bias[112 + 8 * nt + 2 * q + 1];
        *(float2*)&stg[(r0 + g) * LDW + 8 * nt + 2 * q] =
            make_float2(tanhf(acc[0] + b0), tanhf(acc[1] + b1));
        *(float2*)&stg[(r0 + g + 8) * LDW + 8 * nt + 2 * q] =
            make_float2(tanhf(acc[2] + b0), tanhf(acc[3] + b1));
    }
    __syncthreads();
    for (int idx = tid; idx < 128 * 16; idx += 256) {
        int row = idx >> 4, c4 = idx & 15;
        *(float4*)(g_V + ((size_t)b * LL + l0 + row) * CC + 4 * c4) =
            *(float4*)&stg[row * LDW + 4 * c4];
    }
}

// ---------------------------------------------------------------------------
// Kernel 2 (pass1): S fp16 GEMM -> exp2 -> store P + column partials.
// grid (NLT, BB), 256 thr (8 warps x 16 l rows).
// ---------------------------------------------------------------------------
#define LDQH 80        // halves; 40 words -> conflict-free LDS.64

__global__ __launch_bounds__(256, 3) void pass1(void) {
    extern __shared__ char smraw[];
    __half* Qhs = (__half*)smraw;                    // [128][80]
    float* red  = (float*)(smraw + 128 * LDQH * 2);  // [8][128]

    const int tid = threadIdx.x;
    const int lane = tid & 31;
    const int wid = tid >> 5;
    const int g = lane >> 2, q = lane & 3;
    const int b = blockIdx.y;
    const int l0 = blockIdx.x * TL;
    const int r0 = wid * 16;

    uint32_t Ka[4][4];
#pragma unroll
    for (int ks = 0; ks < 4; ks++) {
        uint2 lo = *(const uint2*)(g_Kh + ((size_t)b * LL + l0 + r0 + g) * DK + 16 * ks + 4 * q);
        uint2 hi = *(const uint2*)(g_Kh + ((size_t)b * LL + l0 + r0 + g + 8) * DK + 16 * ks + 4 * q);
        Ka[ks][0] = lo.x; Ka[ks][2] = lo.y;
        Ka[ks][1] = hi.x; Ka[ks][3] = hi.y;
    }

    for (int mt = 0; mt < NMT; mt++) {
        const int m0 = mt * 128;
        __syncthreads();
        for (int idx = tid; idx < 128 * 8; idx += 256) {
            int row = idx >> 3, c8 = idx & 7;
            *(uint4*)&Qhs[row * LDQH + 8 * c8] =
                *(const uint4*)(g_Qh + ((size_t)b * LL + m0 + row) * DK + 8 * c8);
        }
        __syncthreads();

#pragma unroll
        for (int t = 0; t < 8; t++) {
            float a0[4] = {0.f, 0.f, 0.f, 0.f};
            float a1[4] = {0.f, 0.f, 0.f, 0.f};
#pragma unroll
            for (int ks = 0; ks < 4; ks++) {
                uint2 q0 = *(const uint2*)&Qhs[(16 * t + g) * LDQH + 16 * ks + 4 * q];
                uint2 q1 = *(const uint2*)&Qhs[(16 * t + 8 + g) * LDQH + 16 * ks + 4 * q];
                mma16(a0, Ka[ks][0], Ka[ks][1], Ka[ks][2], Ka[ks][3], q0.x, q0.y);
                mma16(a1, Ka[ks][0], Ka[ks][1], Ka[ks][2], Ka[ks][3], q1.x, q1.y);
            }
            float e00 = exp2f(a0[0]), e01 = exp2f(a0[1]), e02 = exp2f(a0[2]), e03 = exp2f(a0[3]);
            float e10 = exp2f(a1[0]), e11 = exp2f(a1[1]), e12 = exp2f(a1[2]), e13 = exp2f(a1[3]);

            uint2 s0; s0.x = packh2(e00, e01); s0.y = packh2(e10, e11);
            uint2 s1; s1.x = packh2(e02, e03); s1.y = packh2(e12, e13);
            *(uint2*)(g_P + ((size_t)b * LL + l0 + r0 + g) * LL + m0 + 16 * t + 4 * q) = s0;
            *(uint2*)(g_P + ((size_t)b * LL + l0 + r0 + g + 8) * LL + m0 + 16 * t + 4 * q) = s1;

            float s00 = e00 + e02, s01 = e01 + e03;   // cols 16t+2q, +1
            float s10 = e10 + e12, s11 = e11 + e13;   // cols 16t+8+2q, +1
#pragma unroll
            for (int off = 4; off < 32; off <<= 1) {
                s00 += __shfl_xor_sync(0xFFFFFFFFu, s00, off);
                s01 += __shfl_xor_sync(0xFFFFFFFFu, s01, off);
                s10 += __shfl_xor_sync(0xFFFFFFFFu, s10, off);
                s11 += __shfl_xor_sync(0xFFFFFFFFu, s11, off);
            }
            if (lane < 4) {
                red[wid * 128 + 16 * t + 2 * q]     = s00;
                red[wid * 128 + 16 * t + 2 * q + 1] = s01;
                red[wid * 128 + 16 * t + 8 + 2 * q]     = s10;
                red[wid * 128 + 16 * t + 8 + 2 * q + 1] = s11;
            }
        }
        __syncthreads();
        if (tid < 128) {
            float s = 0.f;
#pragma unroll
            for (int w = 0; w < 8; w++) s += red[w * 128 + tid];
            g_part[((size_t)blockIdx.x * BB + b) * LL + m0 + tid] = s;
        }
    }
}

// ---------------------------------------------------------------------------
// Kernel 3: cinv; V' = fp16(V*cinv) transposed [c][m'] perm16.
// ---------------------------------------------------------------------------
__global__ void prep_kernel() {
    __shared__ float ci[64];
    __shared__ float vt[64 * 68];
    const int tid = threadIdx.x;
    const int b = blockIdx.y;
    const int m0 = blockIdx.x * 64;

    if (tid < 64) {
        float s = 0.0f;
#pragma unroll
        for (int lt = 0; lt < NLT; lt++)
            s += g_part[((size_t)lt * BB + b) * LL + m0 + tid];
        ci[tid] = 1.0f / s;
    }
    for (int idx = tid; idx < 64 * 16; idx += 256) {
        int row = idx >> 4, c4 = idx & 15;
        *(float4*)&vt[row * 68 + 4 * c4] =
            *(const float4*)(g_V + ((size_t)b * LL + m0 + row) * CC + 4 * c4);
    }
    __syncthreads();
    for (int idx = tid; idx < 64 * 32; idx += 256) {
        int c = idx >> 5, jp = idx & 31;
        int m = 16 * (jp >> 3) + 8 * (jp & 1) + 2 * ((jp >> 1) & 3);
        __half2 hv = __floats2half2_rn(vt[m * 68 + c] * ci[m],
                                       vt[(m + 1) * 68 + c] * ci[m + 1]);
        *(__half2*)(g_Vph + ((size_t)b * CC + c) * LL + m0 + 2 * jp) = hv;
    }
}

// ---------------------------------------------------------------------------
// Kernel 4 (pass2): Y = P @ V', pure fp16 GEMM. grid (16, 32), 128 thr
// (4 warps x 32 l rows). P A-frags streamed from global (depth-2 prefetch),
// V' B-frags from smem, B reuse across 2 row-groups.
// ---------------------------------------------------------------------------
#define LDVH 144       // halves

__global__ __launch_bounds__(128, 4) void pass2(float* __restrict__ out) {
    extern __shared__ char smraw[];
    __half* Vhs = (__half*)smraw;   // [64][144]

    const int tid = threadIdx.x;
    const int lane = tid & 31;
    const int wid = tid >> 5;
    const int g = lane >> 2, q = lane & 3;
    const int b = blockIdx.y;
    const int l0 = blockIdx.x * TL;
    const int r0 = wid * 32;

    float y0[8][4], y1[8][4];
#pragma unroll
    for (int n = 0; n < 8; n++)
#pragma unroll
        for (int e = 0; e < 4; e++) { y0[n][e] = 0.f; y1[n][e] = 0.f; }

    for (int mt = 0; mt < NMT; mt++) {
        const int m0 = mt * 128;
        __syncthreads();
        for (int idx = tid; idx < 64 * 16; idx += 128) {
            int row = idx >> 4, j16 = idx & 15;
            *(uint4*)&Vhs[row * LDVH + 8 * j16] =
                *(const uint4*)(g_Vph + ((size_t)b * CC + row) * LL + m0 + 8 * j16);
        }
        const __half* Pb = g_P + ((size_t)b * LL + l0 + r0 + g) * LL + m0 + 4 * q;
        uint2 bufA[4], bufB[4];
#pragma unroll
        for (int r = 0; r < 4; r++) {
            bufA[r] = *(const uint2*)(Pb + (size_t)(8 * r) * LL);
            bufB[r] = *(const uint2*)(Pb + (size_t)(8 * r) * LL + 16);
        }
        __syncthreads();

#pragma unroll
        for (int t = 0; t < 8; t++) {
            uint2 p0, p1, p2, p3;
            if (t & 1) { p0 = bufB[0]; p1 = bufB[1]; p2 = bufB[2]; p3 = bufB[3]; }
            else       { p0 = bufA[0]; p1 = bufA[1]; p2 = bufA[2]; p3 = bufA[3]; }
            if (t < 6) {
                const __half* Pn = Pb + 16 * (t + 2);
                if (t & 1) {
#pragma unroll
                    for (int r = 0; r < 4; r++) bufB[r] = *(const uint2*)(Pn + (size_t)(8 * r) * LL);
                } else {
#pragma unroll
                    for (int r = 0; r < 4; r++) bufA[r] = *(const uint2*)(Pn + (size_t)(8 * r) * LL);
                }
            }
#pragma unroll
            for (int n = 0; n < 8; n++) {
                uint2 bb = *(const uint2*)&Vhs[(8 * n + g) * LDVH + 16 * t + 4 * q];
                mma16(y0[n], p0.x, p1.x, p0.y, p1.y, bb.x, bb.y);
                mma16(y1[n], p2.x, p3.x, p2.y, p3.y, bb.x, bb.y);
            }
        }
    }

    float* ob0 = out + ((size_t)b * LL + l0 + r0) * CC;
    float* ob1 = out + ((size_t)b * LL + l0 + r0 + 16) * CC;
#pragma unroll
    for (int n = 0; n < 8; n++) {
        *(float2*)&ob0[(size_t)g * CC + 8 * n + 2 * q]       = make_float2(y0[n][0], y0[n][1]);
        *(float2*)&ob0[(size_t)(g + 8) * CC + 8 * n + 2 * q] = make_float2(y0[n][2], y0[n][3]);
        *(float2*)&ob1[(size_t)g * CC + 8 * n + 2 * q]       = make_float2(y1[n][0], y1[n][1]);
        *(float2*)&ob1[(size_t)(g + 8) * CC + 8 * n + 2 * q] = make_float2(y1[n][2], y1[n][3]);
    }
}

// ---------------------------------------------------------------------------
extern "C" void kernel_launch(void* const* d_in, const int* in_sizes, int n_in,
                              void* d_out, int out_size) {
    const float* x  = (const float*)d_in[0];
    const float* Wk = (const float*)d_in[1];
    const float* bk = (const float*)d_in[2];
    const float* Wq = (const float*)d_in[3];
    const float* bq = (const float*)d_in[4];
    const float* Wv = (const float*)d_in[5];
    const float* bv = (const float*)d_in[6];
    const void*  sl = (const void*)d_in[7];
    float* out = (float*)d_out;

    const int kq_smem = KQ_TOT * (int)sizeof(float);
    const int p1_smem = 128 * LDQH * 2 + 8 * 128 * (int)sizeof(float);
    const int p2_smem = 64 * LDVH * 2;

    static bool attr_set = false;
    if (!attr_set) {
        cudaFuncSetAttribute(kqv_mma, cudaFuncAttributeMaxDynamicSharedMemorySize, kq_smem);
        cudaFuncSetAttribute(pass1,   cudaFuncAttributeMaxDynamicSharedMemorySize, p1_smem);
        cudaFuncSetAttribute(pass2,   cudaFuncAttributeMaxDynamicSharedMemorySize, p2_smem);
        attr_set = true;
    }

    dim3 g1(NLT, BB);
    kqv_mma<<<g1, 256, kq_smem>>>(x, Wk, bk, Wq, bq, Wv, bv, sl);

    dim3 g2(NLT, BB);
    pass1<<<g2, 256, p1_smem>>>();

    dim3 g3(LL / 64, BB);
    prep_kernel<<<g3, 256>>>();

    dim3 g4(NLT, BB);
    pass2<<<g4, 128, p2_smem>>>(out);
}

// round 7
// speedup vs baseline: 5.8695x; 1.1971x over previous
#include <cuda_runtime.h>
#include <cuda_fp16.h>
#include <math.h>
#include <stdint.h>

// Problem constants
#define BB 32
#define CC 64
#define LL 2048
#define DD 50
#define DK 64
#define TL 128
#define NLT (LL/TL)    // 16
#define NMT (LL/128)   // 16

// Scratch (device globals — allocation is forbidden)
// g_Kh/g_Qh: fp16, d interleaved within 16-chunks: pos 4q..4q+3 hold d = 2q,2q+1,2q+8,2q+9.
// g_Kh pre-scaled by log2e/sqrt(sample_len).
__device__ __half g_Kh[BB*LL*DK];
__device__ __half g_Qh[BB*LL*DK];
__device__ float  g_V[BB*LL*CC];          // tanh(xWv+bv), [m][c] fp32
__device__ __half g_Vph[BB*CC*LL];        // V' = V*cinv, [c][m'] perm16 on m
__device__ __half g_P[BB*LL*LL];          // P = fp16(exp2(S)), [l][m'] perm16 on m (268MB)
__device__ float  g_part[NLT*BB*LL];      // per-ltile column partials

__device__ __forceinline__ float read_len(const void* p) {
    int i = *(const int*)p;
    if (i > 0 && i < (1 << 24)) return (float)i;
    return __int_as_float(i);
}
__device__ __forceinline__ uint32_t f2tf32(float x) {
    uint32_t u;
    asm("cvt.rna.tf32.f32 %0, %1;" : "=r"(u) : "f"(x));
    return u;
}
__device__ __forceinline__ uint32_t packh2(float lo, float hi) {
    __half2 h = __floats2half2_rn(lo, hi);
    return *(uint32_t*)&h;
}
__device__ __forceinline__ uint32_t ex2h2(uint32_t v) {
    uint32_t r;
    asm("ex2.approx.f16x2 %0, %1;" : "=r"(r) : "r"(v));
    return r;
}
// D += A(16x8 tf32) * B(8x8 tf32)
__device__ __forceinline__ void mma8(float* d, const uint32_t* a, uint32_t b0, uint32_t b1) {
    asm volatile("mma.sync.aligned.m16n8k8.row.col.f32.tf32.tf32.f32 "
                 "{%0,%1,%2,%3}, {%4,%5,%6,%7}, {%8,%9}, {%0,%1,%2,%3};"
                 : "+f"(d[0]), "+f"(d[1]), "+f"(d[2]), "+f"(d[3])
                 : "r"(a[0]), "r"(a[1]), "r"(a[2]), "r"(a[3]), "r"(b0), "r"(b1));
}
// D += A(16x16 f16) * B(16x8 f16)
__device__ __forceinline__ void mma16(float* d, uint32_t a0, uint32_t a1, uint32_t a2,
                                      uint32_t a3, uint32_t b0, uint32_t b1) {
    asm volatile("mma.sync.aligned.m16n8k16.row.col.f32.f16.f16.f32 "
                 "{%0,%1,%2,%3}, {%4,%5,%6,%7}, {%8,%9}, {%0,%1,%2,%3};"
                 : "+f"(d[0]), "+f"(d[1]), "+f"(d[2]), "+f"(d[3])
                 : "r"(a0), "r"(a1), "r"(a2), "r"(a3), "r"(b0), "r"(b1));
}

// ---------------------------------------------------------------------------
// Kernel 1: projections via tf32 mma8. grid (16, 32), 256 thr (8 warps x 16 l).
// ---------------------------------------------------------------------------
#define KQ_XS   0
#define KQ_WS   (KQ_XS + 64*136)
#define KQ_STG  (KQ_WS + 176*72)
#define KQ_BIA  (KQ_STG + 128*72)
#define KQ_TOT  (KQ_BIA + 176)
#define LDX 136
#define LDW 72

__global__ __launch_bounds__(256) void kqv_mma(
        const float* __restrict__ x,
        const float* __restrict__ Wk, const float* __restrict__ bk,
        const float* __restrict__ Wq, const float* __restrict__ bq,
        const float* __restrict__ Wv, const float* __restrict__ bv,
        const void* __restrict__ slp) {
    extern __shared__ float sm[];
    float* xs   = sm + KQ_XS;
    float* Wsm  = sm + KQ_WS;
    float* stg  = sm + KQ_STG;
    float* bias = sm + KQ_BIA;

    const int tid = threadIdx.x;
    const int lane = tid & 31;
    const int wid = tid >> 5;
    const int g = lane >> 2, q = lane & 3;
    const int b = blockIdx.y;
    const int l0 = blockIdx.x * 128;
    const int r0 = wid * 16;
    const float kscale = rsqrtf(read_len(slp)) * 1.4426950408889634f;

    for (int idx = tid; idx < 56 * 64; idx += 256) {
        int d = idx >> 6, c = idx & 63;
        int pos = (c & ~7) | ((c & 3) << 1) | ((c >> 2) & 1);
        Wsm[d * LDW + pos]        = (d < DD) ? __uint_as_float(f2tf32(Wk[c * DD + d])) : 0.0f;
        Wsm[(56 + d) * LDW + pos] = (d < DD) ? __uint_as_float(f2tf32(Wq[c * DD + d])) : 0.0f;
    }
    for (int idx = tid; idx < 64 * 64; idx += 256) {
        int o = idx >> 6, c = idx & 63;
        int pos = (c & ~7) | ((c & 3) << 1) | ((c >> 2) & 1);
        Wsm[(112 + o) * LDW + pos] = __uint_as_float(f2tf32(Wv[c * CC + o]));
    }
    if (tid < 56)  bias[tid]       = (tid < DD) ? bk[tid] : 0.0f;
    if (tid < 56)  bias[56 + tid]  = (tid < DD) ? bq[tid] : 0.0f;
    if (tid < 64)  bias[112 + tid] = bv[tid];

    for (int idx = tid; idx < 64 * 32; idx += 256) {
        int row = idx >> 5, c4 = idx & 31;
        float4 v = *(const float4*)(x + (size_t)b * CC * LL + (size_t)row * LL + l0 + 4 * c4);
        v.x = __uint_as_float(f2tf32(v.x)); v.y = __uint_as_float(f2tf32(v.y));
        v.z = __uint_as_float(f2tf32(v.z)); v.w = __uint_as_float(f2tf32(v.w));
        *(float4*)&xs[row * LDX + 4 * c4] = v;
    }
    __syncthreads();

    uint32_t xa[8][4];
#pragma unroll
    for (int ks = 0; ks < 8; ks++) {
        xa[ks][0] = __float_as_uint(xs[(8 * ks + q) * LDX + r0 + g]);
        xa[ks][1] = __float_as_uint(xs[(8 * ks + q) * LDX + r0 + g + 8]);
        xa[ks][2] = __float_as_uint(xs[(8 * ks + q + 4) * LDX + r0 + g]);
        xa[ks][3] = __float_as_uint(xs[(8 * ks + q + 4) * LDX + r0 + g + 8]);
    }

    // ---- K ----
#pragma unroll
    for (int nt = 0; nt < 7; nt++) {
        float acc[4] = {0.f, 0.f, 0.f, 0.f};
#pragma unroll
        for (int ks = 0; ks < 8; ks++) {
            float2 bb = *(const float2*)&Wsm[(8 * nt + g) * LDW + 8 * ks + 2 * q];
            mma8(acc, xa[ks], __float_as_uint(bb.x), __float_as_uint(bb.y));
        }
        float b0 = bias[8 * nt + 2 * q], b1 = bias[8 * nt + 2 * q + 1];
        float v0 = acc[0] + b0, v1 = acc[1] + b1, v2 = acc[2] + b0, v3 = acc[3] + b1;
        v0 = (v0 > 0.f) ? v0 : expm1f(v0); v1 = (v1 > 0.f) ? v1 : expm1f(v1);
        v2 = (v2 > 0.f) ? v2 : expm1f(v2); v3 = (v3 > 0.f) ? v3 : expm1f(v3);
        *(float2*)&stg[(r0 + g) * LDW + 8 * nt + 2 * q]     = make_float2(v0, v1);
        *(float2*)&stg[(r0 + g + 8) * LDW + 8 * nt + 2 * q] = make_float2(v2, v3);
    }
    for (int idx = tid; idx < 128 * 8; idx += 256)
        stg[(idx >> 3) * LDW + 56 + (idx & 7)] = 0.0f;
    __syncthreads();
    for (int idx = tid; idx < 128 * 32; idx += 256) {
        int row = idx >> 5, p = (idx & 31) * 2;
        int pl = p & 15;
        int d0 = (p & ~15) + 2 * ((pl >> 2) & 3) + 8 * ((pl >> 1) & 1);
        __half2 h = __floats2half2_rn(stg[row * LDW + d0] * kscale,
                                      stg[row * LDW + d0 + 1] * kscale);
        *(__half2*)(g_Kh + ((size_t)b * LL + l0 + row) * DK + p) = h;
    }
    __syncthreads();

    // ---- Q ----
#pragma unroll
    for (int nt = 0; nt < 7; nt++) {
        float acc[4] = {0.f, 0.f, 0.f, 0.f};
#pragma unroll
        for (int ks = 0; ks < 8; ks++) {
            float2 bb = *(const float2*)&Wsm[(56 + 8 * nt + g) * LDW + 8 * ks + 2 * q];
            mma8(acc, xa[ks], __float_as_uint(bb.x), __float_as_uint(bb.y));
        }
        float b0 = bias[56 + 8 * nt + 2 * q], b1 = bias[56 + 8 * nt + 2 * q + 1];
        float v0 = acc[0] + b0, v1 = acc[1] + b1, v2 = acc[2] + b0, v3 = acc[3] + b1;
        v0 = (v0 > 0.f) ? v0 : expm1f(v0); v1 = (v1 > 0.f) ? v1 : expm1f(v1);
        v2 = (v2 > 0.f) ? v2 : expm1f(v2); v3 = (v3 > 0.f) ? v3 : expm1f(v3);
        *(float2*)&stg[(r0 + g) * LDW + 8 * nt + 2 * q]     = make_float2(v0, v1);
        *(float2*)&stg[(r0 + g + 8) * LDW + 8 * nt + 2 * q] = make_float2(v2, v3);
    }
    for (int idx = tid; idx < 128 * 8; idx += 256)
        stg[(idx >> 3) * LDW + 56 + (idx & 7)] = 0.0f;
    __syncthreads();
    for (int idx = tid; idx < 128 * 32; idx += 256) {
        int row = idx >> 5, p = (idx & 31) * 2;
        int pl = p & 15;
        int d0 = (p & ~15) + 2 * ((pl >> 2) & 3) + 8 * ((pl >> 1) & 1);
        __half2 h = __floats2half2_rn(stg[row * LDW + d0], stg[row * LDW + d0 + 1]);
        *(__half2*)(g_Qh + ((size_t)b * LL + l0 + row) * DK + p) = h;
    }
    __syncthreads();

    // ---- V ----
#pragma unroll
    for (int nt = 0; nt < 8; nt++) {
        float acc[4] = {0.f, 0.f, 0.f, 0.f};
#pragma unroll
        for (int ks = 0; ks < 8; ks++) {
            float2 bb = *(const float2*)&Wsm[(112 + 8 * nt + g) * LDW + 8 * ks + 2 * q];
            mma8(acc, xa[ks], __float_as_uint(bb.x), __float_as_uint(bb.y));
        }
        float b0 = bias[112 + 8 * nt + 2 * q], b1 = bias[112 + 8 * nt + 2 * q + 1];
        *(float2*)&stg[(r0 + g) * LDW + 8 * nt + 2 * q] =
            make_float2(tanhf(acc[0] + b0), tanhf(acc[1] + b1));
        *(float2*)&stg[(r0 + g + 8) * LDW + 8 * nt + 2 * q] =
            make_float2(tanhf(acc[2] + b0), tanhf(acc[3] + b1));
    }
    __syncthreads();
    for (int idx = tid; idx < 128 * 16; idx += 256) {
        int row = idx >> 4, c4 = idx & 15;
        *(float4*)(g_V + ((size_t)b * LL + l0 + row) * CC + 4 * c4) =
            *(float4*)&stg[row * LDW + 4 * c4];
    }
}

// ---------------------------------------------------------------------------
// Kernel 2 (pass1): S fp16 GEMM -> ex2.f16x2 -> store P (.cs) + column partials.
// grid (NLT, BB), 256 thr (8 warps x 16 l rows).
// ---------------------------------------------------------------------------
#define LDQH 80        // halves; 40 words -> conflict-free LDS.64

__global__ __launch_bounds__(256, 3) void pass1(void) {
    extern __shared__ char smraw[];
    __half* Qhs = (__half*)smraw;                    // [128][80]
    float* red  = (float*)(smraw + 128 * LDQH * 2);  // [8][128]

    const int tid = threadIdx.x;
    const int lane = tid & 31;
    const int wid = tid >> 5;
    const int g = lane >> 2, q = lane & 3;
    const int b = blockIdx.y;
    const int l0 = blockIdx.x * TL;
    const int r0 = wid * 16;

    uint32_t Ka[4][4];
#pragma unroll
    for (int ks = 0; ks < 4; ks++) {
        uint2 lo = *(const uint2*)(g_Kh + ((size_t)b * LL + l0 + r0 + g) * DK + 16 * ks + 4 * q);
        uint2 hi = *(const uint2*)(g_Kh + ((size_t)b * LL + l0 + r0 + g + 8) * DK + 16 * ks + 4 * q);
        Ka[ks][0] = lo.x; Ka[ks][2] = lo.y;
        Ka[ks][1] = hi.x; Ka[ks][3] = hi.y;
    }

    for (int mt = 0; mt < NMT; mt++) {
        const int m0 = mt * 128;
        __syncthreads();
        for (int idx = tid; idx < 128 * 8; idx += 256) {
            int row = idx >> 3, c8 = idx & 7;
            *(uint4*)&Qhs[row * LDQH + 8 * c8] =
                *(const uint4*)(g_Qh + ((size_t)b * LL + m0 + row) * DK + 8 * c8);
        }
        __syncthreads();

#pragma unroll
        for (int t = 0; t < 8; t++) {
            float a0[4] = {0.f, 0.f, 0.f, 0.f};
            float a1[4] = {0.f, 0.f, 0.f, 0.f};
#pragma unroll
            for (int ks = 0; ks < 4; ks++) {
                uint2 q0 = *(const uint2*)&Qhs[(16 * t + g) * LDQH + 16 * ks + 4 * q];
                uint2 q1 = *(const uint2*)&Qhs[(16 * t + 8 + g) * LDQH + 16 * ks + 4 * q];
                mma16(a0, Ka[ks][0], Ka[ks][1], Ka[ks][2], Ka[ks][3], q0.x, q0.y);
                mma16(a1, Ka[ks][0], Ka[ks][1], Ka[ks][2], Ka[ks][3], q1.x, q1.y);
            }
            // exp via one MUFU per two elements
            uint32_t px0 = ex2h2(packh2(a0[0], a0[1]));   // row g   : (e00, e01)
            uint32_t px1 = ex2h2(packh2(a0[2], a0[3]));   // row g+8 : (e02, e03)
            uint32_t py0 = ex2h2(packh2(a1[0], a1[1]));
            uint32_t py1 = ex2h2(packh2(a1[2], a1[3]));

            uint2 s0; s0.x = px0; s0.y = py0;
            uint2 s1; s1.x = px1; s1.y = py1;
            __stcs((uint2*)(g_P + ((size_t)b * LL + l0 + r0 + g) * LL + m0 + 16 * t + 4 * q), s0);
            __stcs((uint2*)(g_P + ((size_t)b * LL + l0 + r0 + g + 8) * LL + m0 + 16 * t + 4 * q), s1);

            // column partials: HADD2 pairs then 3-level butterfly over g
            __half2 h0 = __hadd2(*(__half2*)&px0, *(__half2*)&px1);  // (s00, s01)
            __half2 h1 = __hadd2(*(__half2*)&py0, *(__half2*)&py1);  // (s10, s11)
#pragma unroll
            for (int off = 4; off < 32; off <<= 1) {
                uint32_t u0 = __shfl_xor_sync(0xFFFFFFFFu, *(uint32_t*)&h0, off);
                uint32_t u1 = __shfl_xor_sync(0xFFFFFFFFu, *(uint32_t*)&h1, off);
                h0 = __hadd2(h0, *(__half2*)&u0);
                h1 = __hadd2(h1, *(__half2*)&u1);
            }
            if (lane < 4) {
                float2 f0 = __half22float2(h0);
                float2 f1 = __half22float2(h1);
                red[wid * 128 + 16 * t + 2 * q]         = f0.x;
                red[wid * 128 + 16 * t + 2 * q + 1]     = f0.y;
                red[wid * 128 + 16 * t + 8 + 2 * q]     = f1.x;
                red[wid * 128 + 16 * t + 8 + 2 * q + 1] = f1.y;
            }
        }
        __syncthreads();
        if (tid < 128) {
            float s = 0.f;
#pragma unroll
            for (int w = 0; w < 8; w++) s += red[w * 128 + tid];
            g_part[((size_t)blockIdx.x * BB + b) * LL + m0 + tid] = s;
        }
    }
}

// ---------------------------------------------------------------------------
// Kernel 3: cinv; V' = fp16(V*cinv) transposed [c][m'] perm16.
// ---------------------------------------------------------------------------
__global__ void prep_kernel() {
    __shared__ float ci[64];
    __shared__ float vt[64 * 68];
    const int tid = threadIdx.x;
    const int b = blockIdx.y;
    const int m0 = blockIdx.x * 64;

    if (tid < 64) {
        float s = 0.0f;
#pragma unroll
        for (int lt = 0; lt < NLT; lt++)
            s += g_part[((size_t)lt * BB + b) * LL + m0 + tid];
        ci[tid] = 1.0f / s;
    }
    for (int idx = tid; idx < 64 * 16; idx += 256) {
        int row = idx >> 4, c4 = idx & 15;
        *(float4*)&vt[row * 68 + 4 * c4] =
            *(const float4*)(g_V + ((size_t)b * LL + m0 + row) * CC + 4 * c4);
    }
    __syncthreads();
    for (int idx = tid; idx < 64 * 32; idx += 256) {
        int c = idx >> 5, jp = idx & 31;
        int m = 16 * (jp >> 3) + 8 * (jp & 1) + 2 * ((jp >> 1) & 3);
        __half2 hv = __floats2half2_rn(vt[m * 68 + c] * ci[m],
                                       vt[(m + 1) * 68 + c] * ci[m + 1]);
        *(__half2*)(g_Vph + ((size_t)b * CC + c) * LL + m0 + 2 * jp) = hv;
    }
}

// ---------------------------------------------------------------------------
// Kernel 4 (pass2): Y = P @ V', pure fp16 GEMM; P streamed with .cs hint.
// grid (16, 32), 128 thr (4 warps x 32 l rows).
// ---------------------------------------------------------------------------
#define LDVH 144       // halves

__global__ __launch_bounds__(128, 4) void pass2(float* __restrict__ out) {
    extern __shared__ char smraw[];
    __half* Vhs = (__half*)smraw;   // [64][144]

    const int tid = threadIdx.x;
    const int lane = tid & 31;
    const int wid = tid >> 5;
    const int g = lane >> 2, q = lane & 3;
    const int b = blockIdx.y;
    const int l0 = blockIdx.x * TL;
    const int r0 = wid * 32;

    float y0[8][4], y1[8][4];
#pragma unroll
    for (int n = 0; n < 8; n++)
#pragma unroll
        for (int e = 0; e < 4; e++) { y0[n][e] = 0.f; y1[n][e] = 0.f; }

    for (int mt = 0; mt < NMT; mt++) {
        const int m0 = mt * 128;
        __syncthreads();
        for (int idx = tid; idx < 64 * 16; idx += 128) {
            int row = idx >> 4, j16 = idx & 15;
            *(uint4*)&Vhs[row * LDVH + 8 * j16] =
                *(const uint4*)(g_Vph + ((size_t)b * CC + row) * LL + m0 + 8 * j16);
        }
        const __half* Pb = g_P + ((size_t)b * LL + l0 + r0 + g) * LL + m0 + 4 * q;
        uint2 bufA[4], bufB[4];
#pragma unroll
        for (int r = 0; r < 4; r++) {
            bufA[r] = __ldcs((const uint2*)(Pb + (size_t)(8 * r) * LL));
            bufB[r] = __ldcs((const uint2*)(Pb + (size_t)(8 * r) * LL + 16));
        }
        __syncthreads();

#pragma unroll
        for (int t = 0; t < 8; t++) {
            uint2 p0, p1, p2, p3;
            if (t & 1) { p0 = bufB[0]; p1 = bufB[1]; p2 = bufB[2]; p3 = bufB[3]; }
            else       { p0 = bufA[0]; p1 = bufA[1]; p2 = bufA[2]; p3 = bufA[3]; }
            if (t < 6) {
                const __half* Pn = Pb + 16 * (t + 2);
                if (t & 1) {
#pragma unroll
                    for (int r = 0; r < 4; r++)
                        bufB[r] = __ldcs((const uint2*)(Pn + (size_t)(8 * r) * LL));
                } else {
#pragma unroll
                    for (int r = 0; r < 4; r++)
                        bufA[r] = __ldcs((const uint2*)(Pn + (size_t)(8 * r) * LL));
                }
            }
#pragma unroll
            for (int n = 0; n < 8; n++) {
                uint2 bb = *(const uint2*)&Vhs[(8 * n + g) * LDVH + 16 * t + 4 * q];
                mma16(y0[n], p0.x, p1.x, p0.y, p1.y, bb.x, bb.y);
                mma16(y1[n], p2.x, p3.x, p2.y, p3.y, bb.x, bb.y);
            }
        }
    }

    float* ob0 = out + ((size_t)b * LL + l0 + r0) * CC;
    float* ob1 = out + ((size_t)b * LL + l0 + r0 + 16) * CC;
#pragma unroll
    for (int n = 0; n < 8; n++) {
        *(float2*)&ob0[(size_t)g * CC + 8 * n + 2 * q]       = make_float2(y0[n][0], y0[n][1]);
        *(float2*)&ob0[(size_t)(g + 8) * CC + 8 * n + 2 * q] = make_float2(y0[n][2], y0[n][3]);
        *(float2*)&ob1[(size_t)g * CC + 8 * n + 2 * q]       = make_float2(y1[n][0], y1[n][1]);
        *(float2*)&ob1[(size_t)(g + 8) * CC + 8 * n + 2 * q] = make_float2(y1[n][2], y1[n][3]);
    }
}

// ---------------------------------------------------------------------------
extern "C" void kernel_launch(void* const* d_in, const int* in_sizes, int n_in,
                              void* d_out, int out_size) {
    const float* x  = (const float*)d_in[0];
    const float* Wk = (const float*)d_in[1];
    const float* bk = (const float*)d_in[2];
    const float* Wq = (const float*)d_in[3];
    const float* bq = (const float*)d_in[4];
    const float* Wv = (const float*)d_in[5];
    const float* bv = (const float*)d_in[6];
    const void*  sl = (const void*)d_in[7];
    float* out = (float*)d_out;

    const int kq_smem = KQ_TOT * (int)sizeof(float);
    const int p1_smem = 128 * LDQH * 2 + 8 * 128 * (int)sizeof(float);
    const int p2_smem = 64 * LDVH * 2;

    static bool attr_set = false;
    if (!attr_set) {
        cudaFuncSetAttribute(kqv_mma, cudaFuncAttributeMaxDynamicSharedMemorySize, kq_smem);
        cudaFuncSetAttribute(pass1,   cudaFuncAttributeMaxDynamicSharedMemorySize, p1_smem);
        cudaFuncSetAttribute(pass2,   cudaFuncAttributeMaxDynamicSharedMemorySize, p2_smem);
        attr_set = true;
    }

    dim3 g1(NLT, BB);
    kqv_mma<<<g1, 256, kq_smem>>>(x, Wk, bk, Wq, bq, Wv, bv, sl);

    dim3 g2(NLT, BB);
    pass1<<<g2, 256, p1_smem>>>();

    dim3 g3(LL / 64, BB);
    prep_kernel<<<g3, 256>>>();

    dim3 g4(NLT, BB);
    pass2<<<g4, 128, p2_smem>>>(out);
}

// round 8
// speedup vs baseline: 6.1577x; 1.0491x over previous
#include <cuda_runtime.h>
#include <cuda_fp16.h>
#include <math.h>
#include <stdint.h>

// Problem constants
#define BB 32
#define CC 64
#define LL 2048
#define DD 50
#define DK 64
#define TL 128
#define NLT (LL/TL)    // 16
#define NMT (LL/128)   // 16

// Scratch (device globals — allocation is forbidden)
// g_Kh/g_Qh: fp16, d interleaved within 16-chunks: pos 4q..4q+3 hold d = 2q,2q+1,2q+8,2q+9.
// g_Kh pre-scaled by log2e/sqrt(sample_len).
__device__ __half g_Kh[BB*LL*DK];
__device__ __half g_Qh[BB*LL*DK];
__device__ float  g_V[BB*LL*CC];          // tanh(xWv+bv), [m][c] fp32
__device__ __half g_Vph[BB*CC*LL];        // V' = V*cinv, [c][m'] perm16 on m
__device__ float  g_part[NLT*BB*LL];      // per-ltile column partials

__device__ __forceinline__ float read_len(const void* p) {
    int i = *(const int*)p;
    if (i > 0 && i < (1 << 24)) return (float)i;
    return __int_as_float(i);
}
__device__ __forceinline__ uint32_t f2tf32(float x) {
    uint32_t u;
    asm("cvt.rna.tf32.f32 %0, %1;" : "=r"(u) : "f"(x));
    return u;
}
__device__ __forceinline__ uint32_t packh2(float lo, float hi) {
    __half2 h = __floats2half2_rn(lo, hi);
    return *(uint32_t*)&h;
}
__device__ __forceinline__ uint32_t ex2h2(uint32_t v) {
    uint32_t r;
    asm("ex2.approx.f16x2 %0, %1;" : "=r"(r) : "r"(v));
    return r;
}
// D += A(16x8 tf32) * B(8x8 tf32)
__device__ __forceinline__ void mma8(float* d, const uint32_t* a, uint32_t b0, uint32_t b1) {
    asm volatile("mma.sync.aligned.m16n8k8.row.col.f32.tf32.tf32.f32 "
                 "{%0,%1,%2,%3}, {%4,%5,%6,%7}, {%8,%9}, {%0,%1,%2,%3};"
                 : "+f"(d[0]), "+f"(d[1]), "+f"(d[2]), "+f"(d[3])
                 : "r"(a[0]), "r"(a[1]), "r"(a[2]), "r"(a[3]), "r"(b0), "r"(b1));
}
// D += A(16x16 f16) * B(16x8 f16)
__device__ __forceinline__ void mma16(float* d, uint32_t a0, uint32_t a1, uint32_t a2,
                                      uint32_t a3, uint32_t b0, uint32_t b1) {
    asm volatile("mma.sync.aligned.m16n8k16.row.col.f32.f16.f16.f32 "
                 "{%0,%1,%2,%3}, {%4,%5,%6,%7}, {%8,%9}, {%0,%1,%2,%3};"
                 : "+f"(d[0]), "+f"(d[1]), "+f"(d[2]), "+f"(d[3])
                 : "r"(a0), "r"(a1), "r"(a2), "r"(a3), "r"(b0), "r"(b1));
}

// ---------------------------------------------------------------------------
// Kernel 1: projections via tf32 mma8. grid (16, 32), 256 thr (8 warps x 16 l).
// ---------------------------------------------------------------------------
#define KQ_XS   0
#define KQ_WS   (KQ_XS + 64*136)
#define KQ_STG  (KQ_WS + 176*72)
#define KQ_BIA  (KQ_STG + 128*72)
#define KQ_TOT  (KQ_BIA + 176)
#define LDX 136
#define LDW 72

__global__ __launch_bounds__(256) void kqv_mma(
        const float* __restrict__ x,
        const float* __restrict__ Wk, const float* __restrict__ bk,
        const float* __restrict__ Wq, const float* __restrict__ bq,
        const float* __restrict__ Wv, const float* __restrict__ bv,
        const void* __restrict__ slp) {
    extern __shared__ float sm[];
    float* xs   = sm + KQ_XS;
    float* Wsm  = sm + KQ_WS;
    float* stg  = sm + KQ_STG;
    float* bias = sm + KQ_BIA;

    const int tid = threadIdx.x;
    const int lane = tid & 31;
    const int wid = tid >> 5;
    const int g = lane >> 2, q = lane & 3;
    const int b = blockIdx.y;
    const int l0 = blockIdx.x * 128;
    const int r0 = wid * 16;
    const float kscale = rsqrtf(read_len(slp)) * 1.4426950408889634f;

    for (int idx = tid; idx < 56 * 64; idx += 256) {
        int d = idx >> 6, c = idx & 63;
        int pos = (c & ~7) | ((c & 3) << 1) | ((c >> 2) & 1);
        Wsm[d * LDW + pos]        = (d < DD) ? __uint_as_float(f2tf32(Wk[c * DD + d])) : 0.0f;
        Wsm[(56 + d) * LDW + pos] = (d < DD) ? __uint_as_float(f2tf32(Wq[c * DD + d])) : 0.0f;
    }
    for (int idx = tid; idx < 64 * 64; idx += 256) {
        int o = idx >> 6, c = idx & 63;
        int pos = (c & ~7) | ((c & 3) << 1) | ((c >> 2) & 1);
        Wsm[(112 + o) * LDW + pos] = __uint_as_float(f2tf32(Wv[c * CC + o]));
    }
    if (tid < 56)  bias[tid]       = (tid < DD) ? bk[tid] : 0.0f;
    if (tid < 56)  bias[56 + tid]  = (tid < DD) ? bq[tid] : 0.0f;
    if (tid < 64)  bias[112 + tid] = bv[tid];

    for (int idx = tid; idx < 64 * 32; idx += 256) {
        int row = idx >> 5, c4 = idx & 31;
        float4 v = *(const float4*)(x + (size_t)b * CC * LL + (size_t)row * LL + l0 + 4 * c4);
        v.x = __uint_as_float(f2tf32(v.x)); v.y = __uint_as_float(f2tf32(v.y));
        v.z = __uint_as_float(f2tf32(v.z)); v.w = __uint_as_float(f2tf32(v.w));
        *(float4*)&xs[row * LDX + 4 * c4] = v;
    }
    __syncthreads();

    uint32_t xa[8][4];
#pragma unroll
    for (int ks = 0; ks < 8; ks++) {
        xa[ks][0] = __float_as_uint(xs[(8 * ks + q) * LDX + r0 + g]);
        xa[ks][1] = __float_as_uint(xs[(8 * ks + q) * LDX + r0 + g + 8]);
        xa[ks][2] = __float_as_uint(xs[(8 * ks + q + 4) * LDX + r0 + g]);
        xa[ks][3] = __float_as_uint(xs[(8 * ks + q + 4) * LDX + r0 + g + 8]);
    }

    // ---- K ----
#pragma unroll
    for (int nt = 0; nt < 7; nt++) {
        float acc[4] = {0.f, 0.f, 0.f, 0.f};
#pragma unroll
        for (int ks = 0; ks < 8; ks++) {
            float2 bb = *(const float2*)&Wsm[(8 * nt + g) * LDW + 8 * ks + 2 * q];
            mma8(acc, xa[ks], __float_as_uint(bb.x), __float_as_uint(bb.y));
        }
        float b0 = bias[8 * nt + 2 * q], b1 = bias[8 * nt + 2 * q + 1];
        float v0 = acc[0] + b0, v1 = acc[1] + b1, v2 = acc[2] + b0, v3 = acc[3] + b1;
        v0 = (v0 > 0.f) ? v0 : expm1f(v0); v1 = (v1 > 0.f) ? v1 : expm1f(v1);
        v2 = (v2 > 0.f) ? v2 : expm1f(v2); v3 = (v3 > 0.f) ? v3 : expm1f(v3);
        *(float2*)&stg[(r0 + g) * LDW + 8 * nt + 2 * q]     = make_float2(v0, v1);
        *(float2*)&stg[(r0 + g + 8) * LDW + 8 * nt + 2 * q] = make_float2(v2, v3);
    }
    for (int idx = tid; idx < 128 * 8; idx += 256)
        stg[(idx >> 3) * LDW + 56 + (idx & 7)] = 0.0f;
    __syncthreads();
    for (int idx = tid; idx < 128 * 32; idx += 256) {
        int row = idx >> 5, p = (idx & 31) * 2;
        int pl = p & 15;
        int d0 = (p & ~15) + 2 * ((pl >> 2) & 3) + 8 * ((pl >> 1) & 1);
        __half2 h = __floats2half2_rn(stg[row * LDW + d0] * kscale,
                                      stg[row * LDW + d0 + 1] * kscale);
        *(__half2*)(g_Kh + ((size_t)b * LL + l0 + row) * DK + p) = h;
    }
    __syncthreads();

    // ---- Q ----
#pragma unroll
    for (int nt = 0; nt < 7; nt++) {
        float acc[4] = {0.f, 0.f, 0.f, 0.f};
#pragma unroll
        for (int ks = 0; ks < 8; ks++) {
            float2 bb = *(const float2*)&Wsm[(56 + 8 * nt + g) * LDW + 8 * ks + 2 * q];
            mma8(acc, xa[ks], __float_as_uint(bb.x), __float_as_uint(bb.y));
        }
        float b0 = bias[56 + 8 * nt + 2 * q], b1 = bias[56 + 8 * nt + 2 * q + 1];
        float v0 = acc[0] + b0, v1 = acc[1] + b1, v2 = acc[2] + b0, v3 = acc[3] + b1;
        v0 = (v0 > 0.f) ? v0 : expm1f(v0); v1 = (v1 > 0.f) ? v1 : expm1f(v1);
        v2 = (v2 > 0.f) ? v2 : expm1f(v2); v3 = (v3 > 0.f) ? v3 : expm1f(v3);
        *(float2*)&stg[(r0 + g) * LDW + 8 * nt + 2 * q]     = make_float2(v0, v1);
        *(float2*)&stg[(r0 + g + 8) * LDW + 8 * nt + 2 * q] = make_float2(v2, v3);
    }
    for (int idx = tid; idx < 128 * 8; idx += 256)
        stg[(idx >> 3) * LDW + 56 + (idx & 7)] = 0.0f;
    __syncthreads();
    for (int idx = tid; idx < 128 * 32; idx += 256) {
        int row = idx >> 5, p = (idx & 31) * 2;
        int pl = p & 15;
        int d0 = (p & ~15) + 2 * ((pl >> 2) & 3) + 8 * ((pl >> 1) & 1);
        __half2 h = __floats2half2_rn(stg[row * LDW + d0], stg[row * LDW + d0 + 1]);
        *(__half2*)(g_Qh + ((size_t)b * LL + l0 + row) * DK + p) = h;
    }
    __syncthreads();

    // ---- V ----
#pragma unroll
    for (int nt = 0; nt < 8; nt++) {
        float acc[4] = {0.f, 0.f, 0.f, 0.f};
#pragma unroll
        for (int ks = 0; ks < 8; ks++) {
            float2 bb = *(const float2*)&Wsm[(112 + 8 * nt + g) * LDW + 8 * ks + 2 * q];
            mma8(acc, xa[ks], __float_as_uint(bb.x), __float_as_uint(bb.y));
        }
        float b0 = bias[112 + 8 * nt + 2 * q], b1 = bias[112 + 8 * nt + 2 * q + 1];
        *(float2*)&stg[(r0 + g) * LDW + 8 * nt + 2 * q] =
            make_float2(tanhf(acc[0] + b0), tanhf(acc[1] + b1));
        *(float2*)&stg[(r0 + g + 8) * LDW + 8 * nt + 2 * q] =
            make_float2(tanhf(acc[2] + b0), tanhf(acc[3] + b1));
    }
    __syncthreads();
    for (int idx = tid; idx < 128 * 16; idx += 256) {
        int row = idx >> 4, c4 = idx & 15;
        *(float4*)(g_V + ((size_t)b * LL + l0 + row) * CC + 4 * c4) =
            *(float4*)&stg[row * LDW + 4 * c4];
    }
}

// ---------------------------------------------------------------------------
// Kernel 2 (pass1): S fp16 GEMM -> ex2.f16x2 -> column partials ONLY (no P).
// grid (NLT, BB), 256 thr (8 warps x 16 l rows).
// ---------------------------------------------------------------------------
#define LDQH 80        // halves; 40 words -> conflict-free LDS.64

__global__ __launch_bounds__(256, 3) void pass1(void) {
    extern __shared__ char smraw[];
    __half* Qhs = (__half*)smraw;                    // [128][80]
    float* red  = (float*)(smraw + 128 * LDQH * 2);  // [8][128]

    const int tid = threadIdx.x;
    const int lane = tid & 31;
    const int wid = tid >> 5;
    const int g = lane >> 2, q = lane & 3;
    const int b = blockIdx.y;
    const int l0 = blockIdx.x * TL;
    const int r0 = wid * 16;

    uint32_t Ka[4][4];
#pragma unroll
    for (int ks = 0; ks < 4; ks++) {
        uint2 lo = *(const uint2*)(g_Kh + ((size_t)b * LL + l0 + r0 + g) * DK + 16 * ks + 4 * q);
        uint2 hi = *(const uint2*)(g_Kh + ((size_t)b * LL + l0 + r0 + g + 8) * DK + 16 * ks + 4 * q);
        Ka[ks][0] = lo.x; Ka[ks][2] = lo.y;
        Ka[ks][1] = hi.x; Ka[ks][3] = hi.y;
    }

    for (int mt = 0; mt < NMT; mt++) {
        const int m0 = mt * 128;
        __syncthreads();
        for (int idx = tid; idx < 128 * 8; idx += 256) {
            int row = idx >> 3, c8 = idx & 7;
            *(uint4*)&Qhs[row * LDQH + 8 * c8] =
                *(const uint4*)(g_Qh + ((size_t)b * LL + m0 + row) * DK + 8 * c8);
        }
        __syncthreads();

#pragma unroll
        for (int t = 0; t < 8; t++) {
            float a0[4] = {0.f, 0.f, 0.f, 0.f};
            float a1[4] = {0.f, 0.f, 0.f, 0.f};
#pragma unroll
            for (int ks = 0; ks < 4; ks++) {
                uint2 q0 = *(const uint2*)&Qhs[(16 * t + g) * LDQH + 16 * ks + 4 * q];
                uint2 q1 = *(const uint2*)&Qhs[(16 * t + 8 + g) * LDQH + 16 * ks + 4 * q];
                mma16(a0, Ka[ks][0], Ka[ks][1], Ka[ks][2], Ka[ks][3], q0.x, q0.y);
                mma16(a1, Ka[ks][0], Ka[ks][1], Ka[ks][2], Ka[ks][3], q1.x, q1.y);
            }
            uint32_t px0 = ex2h2(packh2(a0[0], a0[1]));
            uint32_t px1 = ex2h2(packh2(a0[2], a0[3]));
            uint32_t py0 = ex2h2(packh2(a1[0], a1[1]));
            uint32_t py1 = ex2h2(packh2(a1[2], a1[3]));

            __half2 h0 = __hadd2(*(__half2*)&px0, *(__half2*)&px1);
            __half2 h1 = __hadd2(*(__half2*)&py0, *(__half2*)&py1);
#pragma unroll
            for (int off = 4; off < 32; off <<= 1) {
                uint32_t u0 = __shfl_xor_sync(0xFFFFFFFFu, *(uint32_t*)&h0, off);
                uint32_t u1 = __shfl_xor_sync(0xFFFFFFFFu, *(uint32_t*)&h1, off);
                h0 = __hadd2(h0, *(__half2*)&u0);
                h1 = __hadd2(h1, *(__half2*)&u1);
            }
            if (lane < 4) {
                float2 f0 = __half22float2(h0);
                float2 f1 = __half22float2(h1);
                red[wid * 128 + 16 * t + 2 * q]         = f0.x;
                red[wid * 128 + 16 * t + 2 * q + 1]     = f0.y;
                red[wid * 128 + 16 * t + 8 + 2 * q]     = f1.x;
                red[wid * 128 + 16 * t + 8 + 2 * q + 1] = f1.y;
            }
        }
        __syncthreads();
        if (tid < 128) {
            float s = 0.f;
#pragma unroll
            for (int w = 0; w < 8; w++) s += red[w * 128 + tid];
            g_part[((size_t)blockIdx.x * BB + b) * LL + m0 + tid] = s;
        }
    }
}

// ---------------------------------------------------------------------------
// Kernel 3: cinv; V' = fp16(V*cinv) transposed [c][m'] perm16.
// ---------------------------------------------------------------------------
__global__ void prep_kernel() {
    __shared__ float ci[64];
    __shared__ float vt[64 * 68];
    const int tid = threadIdx.x;
    const int b = blockIdx.y;
    const int m0 = blockIdx.x * 64;

    if (tid < 64) {
        float s = 0.0f;
#pragma unroll
        for (int lt = 0; lt < NLT; lt++)
            s += g_part[((size_t)lt * BB + b) * LL + m0 + tid];
        ci[tid] = 1.0f / s;
    }
    for (int idx = tid; idx < 64 * 16; idx += 256) {
        int row = idx >> 4, c4 = idx & 15;
        *(float4*)&vt[row * 68 + 4 * c4] =
            *(const float4*)(g_V + ((size_t)b * LL + m0 + row) * CC + 4 * c4);
    }
    __syncthreads();
    for (int idx = tid; idx < 64 * 32; idx += 256) {
        int c = idx >> 5, jp = idx & 31;
        int m = 16 * (jp >> 3) + 8 * (jp & 1) + 2 * ((jp >> 1) & 3);
        __half2 hv = __floats2half2_rn(vt[m * 68 + c] * ci[m],
                                       vt[(m + 1) * 68 + c] * ci[m + 1]);
        *(__half2*)(g_Vph + ((size_t)b * CC + c) * LL + m0 + 2 * jp) = hv;
    }
}

// ---------------------------------------------------------------------------
// Kernel 4 (pass2): fused S GEMM -> exp -> Y GEMM, no P materialization.
// grid (NLT, BB), 256 thr (8 warps x 16 l rows). The fp16 GEMM1 C-fragment
// after ex2 IS the fp16 A-fragment of GEMM2 (perm16 V' layout compensates).
// ---------------------------------------------------------------------------
#define LDVH 144       // halves

__global__ __launch_bounds__(256, 3) void pass2(float* __restrict__ out) {
    extern __shared__ char smraw[];
    __half* Qhs = (__half*)smraw;                          // [128][80]
    __half* Vhs = (__half*)(smraw + 128 * LDQH * 2);       // [64][144]

    const int tid = threadIdx.x;
    const int lane = tid & 31;
    const int wid = tid >> 5;
    const int g = lane >> 2, q = lane & 3;
    const int b = blockIdx.y;
    const int l0 = blockIdx.x * TL;
    const int r0 = wid * 16;

    uint32_t Ka[4][4];
#pragma unroll
    for (int ks = 0; ks < 4; ks++) {
        uint2 lo = *(const uint2*)(g_Kh + ((size_t)b * LL + l0 + r0 + g) * DK + 16 * ks + 4 * q);
        uint2 hi = *(const uint2*)(g_Kh + ((size_t)b * LL + l0 + r0 + g + 8) * DK + 16 * ks + 4 * q);
        Ka[ks][0] = lo.x; Ka[ks][2] = lo.y;
        Ka[ks][1] = hi.x; Ka[ks][3] = hi.y;
    }

    float yacc[8][4];
#pragma unroll
    for (int n = 0; n < 8; n++)
#pragma unroll
        for (int e = 0; e < 4; e++) yacc[n][e] = 0.f;

    for (int mt = 0; mt < NMT; mt++) {
        const int m0 = mt * 128;
        __syncthreads();
        for (int idx = tid; idx < 128 * 8; idx += 256) {
            int row = idx >> 3, c8 = idx & 7;
            *(uint4*)&Qhs[row * LDQH + 8 * c8] =
                *(const uint4*)(g_Qh + ((size_t)b * LL + m0 + row) * DK + 8 * c8);
        }
        for (int idx = tid; idx < 64 * 16; idx += 256) {
            int row = idx >> 4, j16 = idx & 15;
            *(uint4*)&Vhs[row * LDVH + 8 * j16] =
                *(const uint4*)(g_Vph + ((size_t)b * CC + row) * LL + m0 + 8 * j16);
        }
        __syncthreads();

#pragma unroll
        for (int t = 0; t < 8; t++) {
            // GEMM1: S rows r0..r0+15, cols 16t..16t+15
            float a0[4] = {0.f, 0.f, 0.f, 0.f};
            float a1[4] = {0.f, 0.f, 0.f, 0.f};
#pragma unroll
            for (int ks = 0; ks < 4; ks++) {
                uint2 q0 = *(const uint2*)&Qhs[(16 * t + g) * LDQH + 16 * ks + 4 * q];
                uint2 q1 = *(const uint2*)&Qhs[(16 * t + 8 + g) * LDQH + 16 * ks + 4 * q];
                mma16(a0, Ka[ks][0], Ka[ks][1], Ka[ks][2], Ka[ks][3], q0.x, q0.y);
                mma16(a1, Ka[ks][0], Ka[ks][1], Ka[ks][2], Ka[ks][3], q1.x, q1.y);
            }
            // exp: C fragment -> fp16 A fragment of GEMM2 (no data movement)
            uint32_t px0 = ex2h2(packh2(a0[0], a0[1]));
            uint32_t px1 = ex2h2(packh2(a0[2], a0[3]));
            uint32_t py0 = ex2h2(packh2(a1[0], a1[1]));
            uint32_t py1 = ex2h2(packh2(a1[2], a1[3]));

            // GEMM2: Y += P(k-block t) @ V'
#pragma unroll
            for (int n = 0; n < 8; n++) {
                uint2 bb = *(const uint2*)&Vhs[(8 * n + g) * LDVH + 16 * t + 4 * q];
                mma16(yacc[n], px0, px1, py0, py1, bb.x, bb.y);
            }
        }
    }

    float* ob = out + ((size_t)b * LL + l0 + r0) * CC;
#pragma unroll
    for (int n = 0; n < 8; n++) {
        *(float2*)&ob[(size_t)g * CC + 8 * n + 2 * q]       = make_float2(yacc[n][0], yacc[n][1]);
        *(float2*)&ob[(size_t)(g + 8) * CC + 8 * n + 2 * q] = make_float2(yacc[n][2], yacc[n][3]);
    }
}

// ---------------------------------------------------------------------------
extern "C" void kernel_launch(void* const* d_in, const int* in_sizes, int n_in,
                              void* d_out, int out_size) {
    const float* x  = (const float*)d_in[0];
    const float* Wk = (const float*)d_in[1];
    const float* bk = (const float*)d_in[2];
    const float* Wq = (const float*)d_in[3];
    const float* bq = (const float*)d_in[4];
    const float* Wv = (const float*)d_in[5];
    const float* bv = (const float*)d_in[6];
    const void*  sl = (const void*)d_in[7];
    float* out = (float*)d_out;

    const int kq_smem = KQ_TOT * (int)sizeof(float);
    const int p1_smem = 128 * LDQH * 2 + 8 * 128 * (int)sizeof(float);
    const int p2_smem = 128 * LDQH * 2 + 64 * LDVH * 2;

    static bool attr_set = false;
    if (!attr_set) {
        cudaFuncSetAttribute(kqv_mma, cudaFuncAttributeMaxDynamicSharedMemorySize, kq_smem);
        cudaFuncSetAttribute(pass1,   cudaFuncAttributeMaxDynamicSharedMemorySize, p1_smem);
        cudaFuncSetAttribute(pass2,   cudaFuncAttributeMaxDynamicSharedMemorySize, p2_smem);
        attr_set = true;
    }

    dim3 g1(NLT, BB);
    kqv_mma<<<g1, 256, kq_smem>>>(x, Wk, bk, Wq, bq, Wv, bv, sl);

    dim3 g2(NLT, BB);
    pass1<<<g2, 256, p1_smem>>>();

    dim3 g3(LL / 64, BB);
    prep_kernel<<<g3, 256>>>();

    dim3 g4(NLT, BB);
    pass2<<<g4, 256, p2_smem>>>(out);
}